// round 5
// baseline (speedup 1.0000x reference)
#include <cuda_runtime.h>
#include <cuda_bf16.h>
#include <cstdint>

#define NMAX 100000
#define D 128

typedef unsigned long long ull;

// Scratch (device globals: allocation-free per harness rules)
__device__ __align__(256) float g_agg[(size_t)NMAX * D];   // mean-aggregated features
__device__ __align__(256) float g_h[(size_t)NMAX * D];     // layer-1 output
__device__ int   g_deg[NMAX];
__device__ int   g_off[NMAX + 1];
__device__ int   g_cur[NMAX];
__device__ int   g_esrc[1600000 + 1024];                   // src sorted by dst (CSR)
__device__ float g_inv[NMAX];
__device__ int   g_idx32;

// ---------------------------------------------------------------------------
__device__ __forceinline__ void split_tf32(float v, uint32_t& hi, uint32_t& lo) {
    asm("cvt.rna.tf32.f32 %0, %1;" : "=r"(hi) : "f"(v));
    float lv = v - __uint_as_float(hi);
    asm("cvt.rna.tf32.f32 %0, %1;" : "=r"(lo) : "f"(lv));
}

#define MMA_TF32(c, a0, a1, a2, a3, b0, b1)                                   \
    asm volatile("mma.sync.aligned.m16n8k8.row.col.f32.tf32.tf32.f32 "        \
                 "{%0,%1,%2,%3},{%4,%5,%6,%7},{%8,%9},{%0,%1,%2,%3};"         \
                 : "+f"((c)[0]), "+f"((c)[1]), "+f"((c)[2]), "+f"((c)[3])     \
                 : "r"(a0), "r"(a1), "r"(a2), "r"(a3), "r"(b0), "r"(b1))

// ---------------------------------------------------------------------------
__global__ void detect_kernel(const void* eidx) {
    const ull* p = (const ull*)eidx;
    int is32 = 0;
    #pragma unroll
    for (int i = 0; i < 4; i++)
        if (p[i] >= (1ULL << 32)) is32 = 1;
    g_idx32 = is32;
}

__device__ __forceinline__ int load_idx(const void* eidx, long long pos) {
    if (g_idx32) return ((const int*)eidx)[pos];
    return (int)(((const long long*)eidx)[pos]);
}

__global__ void deg_kernel(const void* eidx, int nE) {
    int e = blockIdx.x * blockDim.x + threadIdx.x;
    if (e >= nE) return;
    int dst = load_idx(eidx, (long long)nE + e);
    atomicAdd(&g_deg[dst], 1);
}

__global__ void scan_kernel(int nN, int nE) {
    __shared__ int part[1024];
    const int t = threadIdx.x;
    const int chunk = (nN + 1023) / 1024;
    const int start = t * chunk;
    const int end = min(start + chunk, nN);
    int s = 0;
    for (int i = start; i < end; i++) s += g_deg[i];
    part[t] = s;
    __syncthreads();
    for (int off = 1; off < 1024; off <<= 1) {
        int v = (t >= off) ? part[t - off] : 0;
        __syncthreads();
        part[t] += v;
        __syncthreads();
    }
    int run = (t == 0) ? 0 : part[t - 1];
    for (int i = start; i < end; i++) {
        int d = g_deg[i];
        g_off[i] = run;
        g_cur[i] = run;
        g_inv[i] = 1.0f / (float)(d > 0 ? d : 1);
        run += d;
    }
    if (t == 0) g_off[nN] = nE;
}

__global__ void fill_kernel(const void* eidx, int nE) {
    int e = blockIdx.x * blockDim.x + threadIdx.x;
    if (e >= nE) return;
    int src = load_idx(eidx, e);
    int dst = load_idx(eidx, (long long)nE + e);
    int p = atomicAdd(&g_cur[dst], 1);
    g_esrc[p] = src;
}

// ---------------------------------------------------------------------------
// Gather aggregation: one warp per node, lane handles one float4.
__global__ void agg_kernel(const float4* __restrict__ feat, int nN) {
    int gtid = blockIdx.x * blockDim.x + threadIdx.x;
    int w = gtid >> 5;
    int lane = gtid & 31;
    if (w >= nN) return;
    int beg = g_off[w], end = g_off[w + 1];
    float4 a0 = make_float4(0.f, 0.f, 0.f, 0.f);
    float4 a1 = a0;
    int i = beg;
    for (; i + 1 < end; i += 2) {
        int s0 = g_esrc[i], s1 = g_esrc[i + 1];
        float4 v0 = feat[(size_t)s0 * 32 + lane];
        float4 v1 = feat[(size_t)s1 * 32 + lane];
        a0.x += v0.x; a0.y += v0.y; a0.z += v0.z; a0.w += v0.w;
        a1.x += v1.x; a1.y += v1.y; a1.z += v1.z; a1.w += v1.w;
    }
    if (i < end) {
        int s0 = g_esrc[i];
        float4 v0 = feat[(size_t)s0 * 32 + lane];
        a0.x += v0.x; a0.y += v0.y; a0.z += v0.z; a0.w += v0.w;
    }
    float inv = g_inv[w];
    float4 o = make_float4((a0.x + a1.x) * inv, (a0.y + a1.y) * inv,
                           (a0.z + a1.z) * inv, (a0.w + a1.w) * inv);
    ((float4*)g_agg)[(size_t)w * 32 + lane] = o;
}

// ---------------------------------------------------------------------------
// mma.sync tf32 GEMM with 3xTF32 split:
//   out[128-tile, 128] = concat(mean,x)[128, 256] @ concat(Wl;Wr)[256,128] + b
// Block 256 thr (8 warps), warp tile 32x64 (warp_m = wid&3, warp_n = wid>>2).
// K in 4 chunks of 64. SMEM layout (hi/lo interleaved as float2 pairs):
//   A: [row][k]   pos_f2 = row*68 + k              (stride 68 f2 = 544B)
//   B: [n][k]     pos_f2 = n*68 + (k ^ ((n>>2)&15))  (XOR swizzle on k)
#define SROW 544                        // bytes per row (68 float2)
#define SMA_BYTES (128 * SROW)          // 69632
#define SMB_BYTES (128 * SROW)          // 69632
#define SM_TOTAL (SMA_BYTES + SMB_BYTES)  // 139264

template <bool RELU>
__global__ void __launch_bounds__(256, 1)
gemm_mma_kernel(const float* __restrict__ X,
                const float* __restrict__ Wl,
                const float* __restrict__ Wr,
                const float* __restrict__ bias,
                float* __restrict__ out, int nN) {
    extern __shared__ char smem[];
    char* sA = smem;
    char* sB = smem + SMA_BYTES;

    const int tid = threadIdx.x;
    const int wid = tid >> 5;
    const int lane = tid & 31;
    const int g = lane >> 2;        // group 0..7
    const int tg = lane & 3;        // thread-in-group
    const int warp_m = wid & 3;     // rows warp_m*32..+31
    const int warp_n = wid >> 2;    // cols warp_n*64..+63
    const int m0 = blockIdx.x * 128;

    float acc[2][8][4];
    #pragma unroll
    for (int t = 0; t < 2; t++)
        #pragma unroll
        for (int u = 0; u < 8; u++)
            #pragma unroll
            for (int c = 0; c < 4; c++) acc[t][u][c] = 0.f;

    #pragma unroll 1
    for (int kc = 0; kc < 4; kc++) {
        const float* asrc = (kc < 2) ? g_agg : X;
        const float* wsrc = (kc < 2) ? Wl : Wr;
        const int koff = (kc & 1) * 64;

        // ---- stage A: 128 rows x 64 k ----
        #pragma unroll
        for (int it = 0; it < 8; it++) {
            int i = tid + it * 256;          // 0..2047
            int row = i >> 4;
            int q = i & 15;                  // k = q*4
            int node = m0 + row;
            float4 v = make_float4(0.f, 0.f, 0.f, 0.f);
            if (node < nN)
                v = *(const float4*)(asrc + (size_t)node * 128 + koff + q * 4);
            uint4 w0, w1;
            split_tf32(v.x, w0.x, w0.y);
            split_tf32(v.y, w0.z, w0.w);
            split_tf32(v.z, w1.x, w1.y);
            split_tf32(v.w, w1.z, w1.w);
            char* p = sA + row * SROW + q * 32;
            *(uint4*)p = w0;
            *(uint4*)(p + 16) = w1;
        }
        // ---- stage B transposed: B[n][k] = W[koff+k][n], XOR swizzle on k ----
        #pragma unroll
        for (int it = 0; it < 8; it++) {
            int i = tid + it * 256;          // 0..2047
            int k = i >> 5;                  // 0..63
            int nq = i & 31;                 // n0 = nq*4
            float4 v = *(const float4*)(wsrc + (size_t)(koff + k) * 128 + nq * 4);
            int ksw = k ^ (nq & 15);         // (n>>2)&15 == nq&15 for all j<4
            char* p = sB + (size_t)(nq * 4) * SROW + ksw * 8;
            uint2 e;
            split_tf32(v.x, e.x, e.y); *(uint2*)(p) = e;
            split_tf32(v.y, e.x, e.y); *(uint2*)(p + SROW) = e;
            split_tf32(v.z, e.x, e.y); *(uint2*)(p + 2 * SROW) = e;
            split_tf32(v.w, e.x, e.y); *(uint2*)(p + 3 * SROW) = e;
        }
        __syncthreads();

        // ---- MMA over 8 k-steps of 8 ----
        #pragma unroll 2
        for (int ks = 0; ks < 8; ks++) {
            const int k0 = ks * 8;
            // B fragments: 8 n-tiles, hi/lo
            uint32_t bh0[8], bh1[8], bl0[8], bl1[8];
            #pragma unroll
            for (int u = 0; u < 8; u++) {
                int nr = warp_n * 64 + u * 8 + g;
                int swn = (nr >> 2) & 15;
                const char* bp = sB + (size_t)nr * SROW;
                uint2 q0 = *(const uint2*)(bp + ((k0 + tg) ^ swn) * 8);
                uint2 q1 = *(const uint2*)(bp + ((k0 + tg + 4) ^ swn) * 8);
                bh0[u] = q0.x; bl0[u] = q0.y;
                bh1[u] = q1.x; bl1[u] = q1.y;
            }
            #pragma unroll
            for (int t = 0; t < 2; t++) {
                int r0 = warp_m * 32 + t * 16 + g;
                const char* ap0 = sA + (size_t)r0 * SROW;
                const char* ap1 = ap0 + 8 * SROW;
                uint2 a0 = *(const uint2*)(ap0 + (k0 + tg) * 8);
                uint2 a1 = *(const uint2*)(ap1 + (k0 + tg) * 8);
                uint2 a2 = *(const uint2*)(ap0 + (k0 + tg + 4) * 8);
                uint2 a3 = *(const uint2*)(ap1 + (k0 + tg + 4) * 8);
                #pragma unroll
                for (int u = 0; u < 8; u++) {
                    MMA_TF32(acc[t][u], a0.x, a1.x, a2.x, a3.x, bh0[u], bh1[u]);
                    MMA_TF32(acc[t][u], a0.x, a1.x, a2.x, a3.x, bl0[u], bl1[u]);
                    MMA_TF32(acc[t][u], a0.y, a1.y, a2.y, a3.y, bh0[u], bh1[u]);
                }
            }
        }
        __syncthreads();
    }

    // ---- epilogue ----
    #pragma unroll
    for (int u = 0; u < 8; u++) {
        int cb = warp_n * 64 + u * 8 + 2 * tg;
        float2 bv = *(const float2*)(bias + cb);
        #pragma unroll
        for (int t = 0; t < 2; t++) {
            int r0 = m0 + warp_m * 32 + t * 16 + g;
            float2 o0 = make_float2(acc[t][u][0] + bv.x, acc[t][u][1] + bv.y);
            float2 o1 = make_float2(acc[t][u][2] + bv.x, acc[t][u][3] + bv.y);
            if (RELU) {
                o0.x = fmaxf(o0.x, 0.f); o0.y = fmaxf(o0.y, 0.f);
                o1.x = fmaxf(o1.x, 0.f); o1.y = fmaxf(o1.y, 0.f);
            }
            if (r0 < nN)     *(float2*)(out + (size_t)r0 * 128 + cb) = o0;
            if (r0 + 8 < nN) *(float2*)(out + (size_t)(r0 + 8) * 128 + cb) = o1;
        }
    }
}

// ---------------------------------------------------------------------------
extern "C" void kernel_launch(void* const* d_in, const int* in_sizes, int n_in,
                              void* d_out, int out_size) {
    const float* x   = (const float*)d_in[0];
    const void*  eix = d_in[1];
    const float* Wl1 = (const float*)d_in[2];
    const float* Wr1 = (const float*)d_in[3];
    const float* b1  = (const float*)d_in[4];
    const float* Wl2 = (const float*)d_in[5];
    const float* Wr2 = (const float*)d_in[6];
    const float* b2  = (const float*)d_in[7];
    float* out = (float*)d_out;

    const int nN = in_sizes[0] / D;      // 100000
    const int nE = in_sizes[1] / 2;      // 1600000

    void *degp, *hp;
    cudaGetSymbolAddress(&degp, g_deg);
    cudaGetSymbolAddress(&hp,   g_h);
    float* h = (float*)hp;

    cudaFuncSetAttribute(gemm_mma_kernel<true>,
                         cudaFuncAttributeMaxDynamicSharedMemorySize, SM_TOTAL);
    cudaFuncSetAttribute(gemm_mma_kernel<false>,
                         cudaFuncAttributeMaxDynamicSharedMemorySize, SM_TOTAL);

    const int edgeBlocks = (nE + 255) / 256;
    const int aggBlocks  = (int)(((long long)nN * 32 + 255) / 256);
    const int gemmBlocks = (nN + 127) / 128;

    // ---- CSR build (shared by both layers) ----
    cudaMemsetAsync(degp, 0, (size_t)nN * sizeof(int));
    detect_kernel<<<1, 1>>>(eix);
    deg_kernel<<<edgeBlocks, 256>>>(eix, nE);
    scan_kernel<<<1, 1024>>>(nN, nE);
    fill_kernel<<<edgeBlocks, 256>>>(eix, nE);

    // ---- layer 1 ----
    agg_kernel<<<aggBlocks, 256>>>((const float4*)x, nN);
    gemm_mma_kernel<true><<<gemmBlocks, 256, SM_TOTAL>>>(x, Wl1, Wr1, b1, h, nN);

    // ---- layer 2 ----
    agg_kernel<<<aggBlocks, 256>>>((const float4*)h, nN);
    gemm_mma_kernel<false><<<gemmBlocks, 256, SM_TOTAL>>>(h, Wl2, Wr2, b2, out, nN);
}

// round 6
// speedup vs baseline: 1.2333x; 1.2333x over previous
#include <cuda_runtime.h>
#include <cuda_bf16.h>
#include <cstdint>

#define NMAX 100000
#define D 128

typedef unsigned long long ull;

// Scratch (device globals: allocation-free per harness rules)
__device__ __align__(256) float g_agg[(size_t)NMAX * D];   // mean-aggregated features
__device__ __align__(256) float g_h[(size_t)NMAX * D];     // layer-1 output
__device__ __align__(16)  char  g_Wb[327680];              // pre-split weights (bf16 hi/lo)
__device__ int   g_deg[NMAX];
__device__ int   g_off[NMAX + 1];
__device__ int   g_cur[NMAX];
__device__ int   g_esrc[1600000 + 1024];                   // src sorted by dst (CSR)
__device__ float g_inv[NMAX];
__device__ int   g_idx32;

// ---------------------------------------------------------------------------
// Split fp32 into two bf16 (hi + lo), packed as bf16x2 pairs for (v0, v1):
// returns hi2 = {bf16(v1)<<16 | bf16(v0)}, lo2 likewise for the residuals.
__device__ __forceinline__ void split2_bf16(float v0, float v1,
                                            uint32_t& hi2, uint32_t& lo2) {
    asm("cvt.rn.bf16x2.f32 %0, %1, %2;" : "=r"(hi2) : "f"(v1), "f"(v0));
    float h0 = __uint_as_float(hi2 << 16);
    float h1 = __uint_as_float(hi2 & 0xffff0000u);
    float l0 = v0 - h0, l1 = v1 - h1;
    asm("cvt.rn.bf16x2.f32 %0, %1, %2;" : "=r"(lo2) : "f"(l1), "f"(l0));
}

#define MMA_BF16(c, a0, a1, a2, a3, b0, b1)                                   \
    asm volatile("mma.sync.aligned.m16n8k16.row.col.f32.bf16.bf16.f32 "       \
                 "{%0,%1,%2,%3},{%4,%5,%6,%7},{%8,%9},{%0,%1,%2,%3};"         \
                 : "+f"((c)[0]), "+f"((c)[1]), "+f"((c)[2]), "+f"((c)[3])     \
                 : "r"(a0), "r"(a1), "r"(a2), "r"(a3), "r"(b0), "r"(b1))

// ---------------------------------------------------------------------------
__global__ void detect_kernel(const void* eidx) {
    const ull* p = (const ull*)eidx;
    int is32 = 0;
    #pragma unroll
    for (int i = 0; i < 4; i++)
        if (p[i] >= (1ULL << 32)) is32 = 1;
    g_idx32 = is32;
}

__device__ __forceinline__ int load_idx(const void* eidx, long long pos) {
    if (g_idx32) return ((const int*)eidx)[pos];
    return (int)(((const long long*)eidx)[pos]);
}

__global__ void deg_kernel(const void* eidx, int nE) {
    int e = blockIdx.x * blockDim.x + threadIdx.x;
    if (e >= nE) return;
    int dst = load_idx(eidx, (long long)nE + e);
    atomicAdd(&g_deg[dst], 1);
}

__global__ void scan_kernel(int nN, int nE) {
    __shared__ int part[1024];
    const int t = threadIdx.x;
    const int chunk = (nN + 1023) / 1024;
    const int start = t * chunk;
    const int end = min(start + chunk, nN);
    int s = 0;
    for (int i = start; i < end; i++) s += g_deg[i];
    part[t] = s;
    __syncthreads();
    for (int off = 1; off < 1024; off <<= 1) {
        int v = (t >= off) ? part[t - off] : 0;
        __syncthreads();
        part[t] += v;
        __syncthreads();
    }
    int run = (t == 0) ? 0 : part[t - 1];
    for (int i = start; i < end; i++) {
        int d = g_deg[i];
        g_off[i] = run;
        g_cur[i] = run;
        g_inv[i] = 1.0f / (float)(d > 0 ? d : 1);
        run += d;
    }
    if (t == 0) g_off[nN] = nE;
}

__global__ void fill_kernel(const void* eidx, int nE) {
    int e = blockIdx.x * blockDim.x + threadIdx.x;
    if (e >= nE) return;
    int src = load_idx(eidx, e);
    int dst = load_idx(eidx, (long long)nE + e);
    int p = atomicAdd(&g_cur[dst], 1);
    g_esrc[p] = src;
}

// ---------------------------------------------------------------------------
// Gather aggregation: one warp per node, lane handles one float4. 4-wide MLP.
__global__ void agg_kernel(const float4* __restrict__ feat, int nN) {
    int gtid = blockIdx.x * blockDim.x + threadIdx.x;
    int w = gtid >> 5;
    int lane = gtid & 31;
    if (w >= nN) return;
    int beg = g_off[w], end = g_off[w + 1];
    float4 a0 = make_float4(0.f, 0.f, 0.f, 0.f);
    float4 a1 = a0;
    int i = beg;
    for (; i + 3 < end; i += 4) {
        int s0 = g_esrc[i], s1 = g_esrc[i + 1];
        int s2 = g_esrc[i + 2], s3 = g_esrc[i + 3];
        float4 v0 = feat[(size_t)s0 * 32 + lane];
        float4 v1 = feat[(size_t)s1 * 32 + lane];
        float4 v2 = feat[(size_t)s2 * 32 + lane];
        float4 v3 = feat[(size_t)s3 * 32 + lane];
        a0.x += v0.x; a0.y += v0.y; a0.z += v0.z; a0.w += v0.w;
        a1.x += v1.x; a1.y += v1.y; a1.z += v1.z; a1.w += v1.w;
        a0.x += v2.x; a0.y += v2.y; a0.z += v2.z; a0.w += v2.w;
        a1.x += v3.x; a1.y += v3.y; a1.z += v3.z; a1.w += v3.w;
    }
    for (; i < end; i++) {
        int s0 = g_esrc[i];
        float4 v0 = feat[(size_t)s0 * 32 + lane];
        a0.x += v0.x; a0.y += v0.y; a0.z += v0.z; a0.w += v0.w;
    }
    float inv = g_inv[w];
    float4 o = make_float4((a0.x + a1.x) * inv, (a0.y + a1.y) * inv,
                           (a0.z + a1.z) * inv, (a0.w + a1.w) * inv);
    ((float4*)g_agg)[(size_t)w * 32 + lane] = o;
}

// ---------------------------------------------------------------------------
// Pre-split weights into the exact staged-B smem image.
// Layout per layer (163840 B): chunk kc (0..3: kc<2 from Wl, else Wr) 40960 B;
// within chunk: n (0..127) rows of 320 B; within row: ks (0..3) groups of 64 B;
// within group: 8 positions of 8 B = {hi2, lo2}, kpair p at pos 2*(p&3)+(p>>2).
__global__ void wconv_kernel(const float* __restrict__ Wl1, const float* __restrict__ Wr1,
                             const float* __restrict__ Wl2, const float* __restrict__ Wr2) {
    int unit = blockIdx.x * 256 + threadIdx.x;   // 4096 units
    if (unit >= 4096) return;
    int layer = unit >> 11;
    int rem = unit & 2047;
    int kc = rem >> 9;
    int rem2 = rem & 511;
    int n = rem2 >> 2;
    int ks = rem2 & 3;
    const float* Wsrc = (layer == 0) ? ((kc < 2) ? Wl1 : Wr1)
                                     : ((kc < 2) ? Wl2 : Wr2);
    int kbase = (kc & 1) * 64 + ks * 16;
    char* dst = g_Wb + layer * 163840 + kc * 40960 + n * 320 + ks * 64;
    uint32_t buf[16];
    #pragma unroll
    for (int p = 0; p < 8; p++) {
        float v0 = Wsrc[(kbase + 2 * p) * 128 + n];      // B[n][k] = W[k][n]
        float v1 = Wsrc[(kbase + 2 * p + 1) * 128 + n];
        uint32_t hi2, lo2;
        split2_bf16(v0, v1, hi2, lo2);
        int pos = 2 * (p & 3) + (p >> 2);
        buf[pos * 2] = hi2;
        buf[pos * 2 + 1] = lo2;
    }
    #pragma unroll
    for (int q = 0; q < 4; q++)
        ((uint4*)dst)[q] = make_uint4(buf[4 * q], buf[4 * q + 1],
                                      buf[4 * q + 2], buf[4 * q + 3]);
}

// ---------------------------------------------------------------------------
// bf16-split mma.sync GEMM:
//   out[128-tile, 128] = concat(mean,x)[128,256] @ concat(Wl;Wr)[256,128] + b
// Block 256 thr (8 warps), warp tile 32x64. K in 4 chunks of 64.
// SMEM: A 128x320B (same image as B), B 128x320B -> 81920 B, 2 CTAs/SM.
#define RS 320
#define SMA_BYTES (128 * RS)
#define SM_TOTAL (2 * 128 * RS)   // 81920

template <bool RELU>
__global__ void __launch_bounds__(256, 2)
gemm_bf16_kernel(const float* __restrict__ X, int layer,
                 const float* __restrict__ bias,
                 float* __restrict__ out, int nN) {
    extern __shared__ char smem[];
    char* sA = smem;
    char* sB = smem + SMA_BYTES;

    const int tid = threadIdx.x;
    const int wid = tid >> 5;
    const int lane = tid & 31;
    const int g = lane >> 2;
    const int tg = lane & 3;
    const int warp_m = wid & 3;     // rows warp_m*32..+31
    const int warp_n = wid >> 2;    // cols warp_n*64..+63
    const int m0 = blockIdx.x * 128;
    const char* wbase = g_Wb + layer * 163840;

    float acc[2][8][4];
    #pragma unroll
    for (int t = 0; t < 2; t++)
        #pragma unroll
        for (int u = 0; u < 8; u++)
            #pragma unroll
            for (int c = 0; c < 4; c++) acc[t][u][c] = 0.f;

    #pragma unroll 1
    for (int kc = 0; kc < 4; kc++) {
        const float* asrc = (kc < 2) ? g_agg : X;
        const int koff = (kc & 1) * 64;
        if (kc > 0) __syncthreads();

        // ---- stage A: split fp32 -> bf16 hi/lo in staged image ----
        #pragma unroll
        for (int it = 0; it < 2; it++) {
            int unit = tid + it * 256;      // 0..511: row*4 + ks
            int row = unit >> 2, ks = unit & 3;
            int node = m0 + row;
            float4 f0 = make_float4(0.f, 0.f, 0.f, 0.f), f1 = f0, f2 = f0, f3 = f0;
            if (node < nN) {
                const float4* s = (const float4*)(asrc + (size_t)node * 128 + koff + ks * 16);
                f0 = s[0]; f1 = s[1]; f2 = s[2]; f3 = s[3];
            }
            float v[16] = {f0.x, f0.y, f0.z, f0.w, f1.x, f1.y, f1.z, f1.w,
                           f2.x, f2.y, f2.z, f2.w, f3.x, f3.y, f3.z, f3.w};
            uint32_t buf[16];
            #pragma unroll
            for (int p = 0; p < 8; p++) {
                uint32_t hi2, lo2;
                split2_bf16(v[2 * p], v[2 * p + 1], hi2, lo2);
                int pos = 2 * (p & 3) + (p >> 2);
                buf[pos * 2] = hi2;
                buf[pos * 2 + 1] = lo2;
            }
            char* dst = sA + row * RS + ks * 64;
            #pragma unroll
            for (int q = 0; q < 4; q++)
                ((uint4*)dst)[q] = make_uint4(buf[4 * q], buf[4 * q + 1],
                                              buf[4 * q + 2], buf[4 * q + 3]);
        }
        // ---- stage B: flat copy of pre-split image (40960 B) ----
        {
            const uint4* src = (const uint4*)(wbase + kc * 40960);
            uint4* dst = (uint4*)sB;
            #pragma unroll
            for (int it = 0; it < 10; it++) {
                int idx = tid + it * 256;   // 2560 uint4
                dst[idx] = src[idx];
            }
        }
        __syncthreads();

        // ---- MMA: 4 k-steps of 16 ----
        #pragma unroll
        for (int ks = 0; ks < 4; ks++) {
            uint32_t aH[2][4], aL[2][4];
            #pragma unroll
            for (int t = 0; t < 2; t++) {
                int r = warp_m * 32 + t * 16 + g;
                uint4 q0 = *(const uint4*)(sA + r * RS + ks * 64 + tg * 16);
                uint4 q1 = *(const uint4*)(sA + (r + 8) * RS + ks * 64 + tg * 16);
                aH[t][0] = q0.x; aH[t][1] = q1.x; aH[t][2] = q0.z; aH[t][3] = q1.z;
                aL[t][0] = q0.y; aL[t][1] = q1.y; aL[t][2] = q0.w; aL[t][3] = q1.w;
            }
            #pragma unroll
            for (int ug = 0; ug < 2; ug++) {
                #pragma unroll
                for (int uu = 0; uu < 4; uu++) {
                    int u = ug * 4 + uu;
                    int n = warp_n * 64 + u * 8 + g;
                    uint4 qb = *(const uint4*)(sB + n * RS + ks * 64 + tg * 16);
                    // qb = {b0hi, b0lo, b1hi, b1lo}
                    #pragma unroll
                    for (int t = 0; t < 2; t++) {
                        MMA_BF16(acc[t][u], aH[t][0], aH[t][1], aH[t][2], aH[t][3], qb.x, qb.z);
                        MMA_BF16(acc[t][u], aH[t][0], aH[t][1], aH[t][2], aH[t][3], qb.y, qb.w);
                        MMA_BF16(acc[t][u], aL[t][0], aL[t][1], aL[t][2], aL[t][3], qb.x, qb.z);
                    }
                }
            }
        }
    }

    // ---- epilogue ----
    #pragma unroll
    for (int u = 0; u < 8; u++) {
        int cb = warp_n * 64 + u * 8 + 2 * tg;
        float2 bv = *(const float2*)(bias + cb);
        #pragma unroll
        for (int t = 0; t < 2; t++) {
            int r0 = m0 + warp_m * 32 + t * 16 + g;
            float2 o0 = make_float2(acc[t][u][0] + bv.x, acc[t][u][1] + bv.y);
            float2 o1 = make_float2(acc[t][u][2] + bv.x, acc[t][u][3] + bv.y);
            if (RELU) {
                o0.x = fmaxf(o0.x, 0.f); o0.y = fmaxf(o0.y, 0.f);
                o1.x = fmaxf(o1.x, 0.f); o1.y = fmaxf(o1.y, 0.f);
            }
            if (r0 < nN)     *(float2*)(out + (size_t)r0 * 128 + cb) = o0;
            if (r0 + 8 < nN) *(float2*)(out + (size_t)(r0 + 8) * 128 + cb) = o1;
        }
    }
}

// ---------------------------------------------------------------------------
extern "C" void kernel_launch(void* const* d_in, const int* in_sizes, int n_in,
                              void* d_out, int out_size) {
    const float* x   = (const float*)d_in[0];
    const void*  eix = d_in[1];
    const float* Wl1 = (const float*)d_in[2];
    const float* Wr1 = (const float*)d_in[3];
    const float* b1  = (const float*)d_in[4];
    const float* Wl2 = (const float*)d_in[5];
    const float* Wr2 = (const float*)d_in[6];
    const float* b2  = (const float*)d_in[7];
    float* out = (float*)d_out;

    const int nN = in_sizes[0] / D;      // 100000
    const int nE = in_sizes[1] / 2;      // 1600000

    void *degp, *hp;
    cudaGetSymbolAddress(&degp, g_deg);
    cudaGetSymbolAddress(&hp,   g_h);
    float* h = (float*)hp;

    cudaFuncSetAttribute(gemm_bf16_kernel<true>,
                         cudaFuncAttributeMaxDynamicSharedMemorySize, SM_TOTAL);
    cudaFuncSetAttribute(gemm_bf16_kernel<false>,
                         cudaFuncAttributeMaxDynamicSharedMemorySize, SM_TOTAL);

    const int edgeBlocks = (nE + 255) / 256;
    const int aggBlocks  = (int)(((long long)nN * 32 + 255) / 256);
    const int gemmBlocks = (nN + 127) / 128;

    // ---- CSR build + weight pre-split (shared by both layers) ----
    cudaMemsetAsync(degp, 0, (size_t)nN * sizeof(int));
    detect_kernel<<<1, 1>>>(eix);
    wconv_kernel<<<16, 256>>>(Wl1, Wr1, Wl2, Wr2);
    deg_kernel<<<edgeBlocks, 256>>>(eix, nE);
    scan_kernel<<<1, 1024>>>(nN, nE);
    fill_kernel<<<edgeBlocks, 256>>>(eix, nE);

    // ---- layer 1 ----
    agg_kernel<<<aggBlocks, 256>>>((const float4*)x, nN);
    gemm_bf16_kernel<true><<<gemmBlocks, 256, SM_TOTAL>>>(x, 0, b1, h, nN);

    // ---- layer 2 ----
    agg_kernel<<<aggBlocks, 256>>>((const float4*)h, nN);
    gemm_bf16_kernel<false><<<gemmBlocks, 256, SM_TOTAL>>>(h, 1, b2, out, nN);
}

// round 7
// speedup vs baseline: 1.9751x; 1.6016x over previous
#include <cuda_runtime.h>
#include <cuda_bf16.h>
#include <cstdint>

#define NMAX 100000
#define D 128

typedef unsigned long long ull;

// Scratch (device globals: allocation-free per harness rules)
__device__ __align__(256) float g_agg[(size_t)NMAX * D];   // mean-aggregated features
__device__ __align__(256) float g_h[(size_t)NMAX * D];     // layer-1 output
__device__ __align__(16)  char  g_Wb[327680];              // pre-split weights (bf16 hi/lo)
__device__ int   g_deg[NMAX];
__device__ int   g_off[NMAX + 1];
__device__ int   g_cur[NMAX];
__device__ int   g_esrc[1600000 + 1024];                   // src sorted by dst (CSR)
__device__ float g_inv[NMAX];
__device__ int   g_part[256];                              // per-block partial sums
__device__ int   g_pbase[256];                             // exclusive base per block
__device__ int   g_idx32;

// ---------------------------------------------------------------------------
// Split fp32 into two bf16 (hi + lo), packed as bf16x2 pairs for (v0, v1).
__device__ __forceinline__ void split2_bf16(float v0, float v1,
                                            uint32_t& hi2, uint32_t& lo2) {
    asm("cvt.rn.bf16x2.f32 %0, %1, %2;" : "=r"(hi2) : "f"(v1), "f"(v0));
    float h0 = __uint_as_float(hi2 << 16);
    float h1 = __uint_as_float(hi2 & 0xffff0000u);
    float l0 = v0 - h0, l1 = v1 - h1;
    asm("cvt.rn.bf16x2.f32 %0, %1, %2;" : "=r"(lo2) : "f"(l1), "f"(l0));
}

#define MMA_BF16(c, a0, a1, a2, a3, b0, b1)                                   \
    asm volatile("mma.sync.aligned.m16n8k16.row.col.f32.bf16.bf16.f32 "       \
                 "{%0,%1,%2,%3},{%4,%5,%6,%7},{%8,%9},{%0,%1,%2,%3};"         \
                 : "+f"((c)[0]), "+f"((c)[1]), "+f"((c)[2]), "+f"((c)[3])     \
                 : "r"(a0), "r"(a1), "r"(a2), "r"(a3), "r"(b0), "r"(b1))

// ---------------------------------------------------------------------------
__global__ void detect_kernel(const void* eidx) {
    const ull* p = (const ull*)eidx;
    int is32 = 0;
    #pragma unroll
    for (int i = 0; i < 4; i++)
        if (p[i] >= (1ULL << 32)) is32 = 1;
    g_idx32 = is32;
}

__device__ __forceinline__ int load_idx(const void* eidx, long long pos) {
    if (g_idx32) return ((const int*)eidx)[pos];
    return (int)(((const long long*)eidx)[pos]);
}

__global__ void deg_kernel(const void* eidx, int nE) {
    int e = blockIdx.x * blockDim.x + threadIdx.x;
    if (e >= nE) return;
    int dst = load_idx(eidx, (long long)nE + e);
    atomicAdd(&g_deg[dst], 1);
}

// ---------------------------------------------------------------------------
// Parallel 3-phase exclusive scan over degrees (1024 elements per block).
__global__ void blocksum_kernel(int nN) {
    __shared__ int ws[8];
    int t = threadIdx.x;
    int base = blockIdx.x * 1024 + t * 4;
    int s = 0;
    #pragma unroll
    for (int j = 0; j < 4; j++) {
        int i = base + j;
        if (i < nN) s += g_deg[i];
    }
    #pragma unroll
    for (int o = 16; o > 0; o >>= 1) s += __shfl_down_sync(~0u, s, o);
    if ((t & 31) == 0) ws[t >> 5] = s;
    __syncthreads();
    if (t < 8) {
        int v = ws[t];
        #pragma unroll
        for (int o = 4; o > 0; o >>= 1) v += __shfl_down_sync(0xff, v, o);
        if (t == 0) g_part[blockIdx.x] = v;
    }
}

__global__ void scanpart_kernel(int nb) {
    __shared__ int sm[128];
    int t = threadIdx.x;
    int v = (t < nb) ? g_part[t] : 0;
    sm[t] = v;
    __syncthreads();
    for (int o = 1; o < 128; o <<= 1) {
        int u = (t >= o) ? sm[t - o] : 0;
        __syncthreads();
        sm[t] += u;
        __syncthreads();
    }
    g_pbase[t] = (t == 0) ? 0 : sm[t - 1];
}

__global__ void offsets_kernel(int nN, int nE) {
    __shared__ int warp_tot[8];
    int t = threadIdx.x;
    int blk = blockIdx.x;
    int lane = t & 31, w = t >> 5;
    int base = blk * 1024 + t * 4;
    int d[4];
    int s = 0;
    #pragma unroll
    for (int j = 0; j < 4; j++) {
        int i = base + j;
        d[j] = (i < nN) ? g_deg[i] : 0;
        s += d[j];
    }
    int inc = s;
    #pragma unroll
    for (int o = 1; o < 32; o <<= 1) {
        int u = __shfl_up_sync(~0u, inc, o);
        if (lane >= o) inc += u;
    }
    if (lane == 31) warp_tot[w] = inc;
    __syncthreads();
    if (t < 8) {
        int v = warp_tot[t];
        #pragma unroll
        for (int o = 1; o < 8; o <<= 1) {
            int u = __shfl_up_sync(0xff, v, o);
            if (t >= o) v += u;
        }
        warp_tot[t] = v;
    }
    __syncthreads();
    int run = g_pbase[blk] + (inc - s) + ((w > 0) ? warp_tot[w - 1] : 0);
    #pragma unroll
    for (int j = 0; j < 4; j++) {
        int i = base + j;
        if (i < nN) {
            g_off[i] = run;
            g_cur[i] = run;
            g_inv[i] = 1.0f / (float)(d[j] > 0 ? d[j] : 1);
            run += d[j];
        }
    }
    if (blk == 0 && t == 0) g_off[nN] = nE;
}

__global__ void fill_kernel(const void* eidx, int nE) {
    int e = blockIdx.x * blockDim.x + threadIdx.x;
    if (e >= nE) return;
    int src = load_idx(eidx, e);
    int dst = load_idx(eidx, (long long)nE + e);
    int p = atomicAdd(&g_cur[dst], 1);
    g_esrc[p] = src;
}

// ---------------------------------------------------------------------------
// Gather aggregation: one warp per node, lane handles one float4. 4-wide MLP.
__global__ void agg_kernel(const float4* __restrict__ feat, int nN) {
    int gtid = blockIdx.x * blockDim.x + threadIdx.x;
    int w = gtid >> 5;
    int lane = gtid & 31;
    if (w >= nN) return;
    int beg = g_off[w], end = g_off[w + 1];
    float4 a0 = make_float4(0.f, 0.f, 0.f, 0.f);
    float4 a1 = a0;
    int i = beg;
    for (; i + 3 < end; i += 4) {
        int s0 = g_esrc[i], s1 = g_esrc[i + 1];
        int s2 = g_esrc[i + 2], s3 = g_esrc[i + 3];
        float4 v0 = feat[(size_t)s0 * 32 + lane];
        float4 v1 = feat[(size_t)s1 * 32 + lane];
        float4 v2 = feat[(size_t)s2 * 32 + lane];
        float4 v3 = feat[(size_t)s3 * 32 + lane];
        a0.x += v0.x; a0.y += v0.y; a0.z += v0.z; a0.w += v0.w;
        a1.x += v1.x; a1.y += v1.y; a1.z += v1.z; a1.w += v1.w;
        a0.x += v2.x; a0.y += v2.y; a0.z += v2.z; a0.w += v2.w;
        a1.x += v3.x; a1.y += v3.y; a1.z += v3.z; a1.w += v3.w;
    }
    for (; i < end; i++) {
        int s0 = g_esrc[i];
        float4 v0 = feat[(size_t)s0 * 32 + lane];
        a0.x += v0.x; a0.y += v0.y; a0.z += v0.z; a0.w += v0.w;
    }
    float inv = g_inv[w];
    float4 o = make_float4((a0.x + a1.x) * inv, (a0.y + a1.y) * inv,
                           (a0.z + a1.z) * inv, (a0.w + a1.w) * inv);
    ((float4*)g_agg)[(size_t)w * 32 + lane] = o;
}

// ---------------------------------------------------------------------------
// Pre-split weights into the exact staged-B smem image. See R6 layout notes.
__global__ void wconv_kernel(const float* __restrict__ Wl1, const float* __restrict__ Wr1,
                             const float* __restrict__ Wl2, const float* __restrict__ Wr2) {
    int unit = blockIdx.x * 256 + threadIdx.x;   // 4096 units
    if (unit >= 4096) return;
    int layer = unit >> 11;
    int rem = unit & 2047;
    int kc = rem >> 9;
    int rem2 = rem & 511;
    int n = rem2 >> 2;
    int ks = rem2 & 3;
    const float* Wsrc = (layer == 0) ? ((kc < 2) ? Wl1 : Wr1)
                                     : ((kc < 2) ? Wl2 : Wr2);
    int kbase = (kc & 1) * 64 + ks * 16;
    char* dst = g_Wb + layer * 163840 + kc * 40960 + n * 320 + ks * 64;
    uint32_t buf[16];
    #pragma unroll
    for (int p = 0; p < 8; p++) {
        float v0 = Wsrc[(kbase + 2 * p) * 128 + n];      // B[n][k] = W[k][n]
        float v1 = Wsrc[(kbase + 2 * p + 1) * 128 + n];
        uint32_t hi2, lo2;
        split2_bf16(v0, v1, hi2, lo2);
        int pos = 2 * (p & 3) + (p >> 2);
        buf[pos * 2] = hi2;
        buf[pos * 2 + 1] = lo2;
    }
    #pragma unroll
    for (int q = 0; q < 4; q++)
        ((uint4*)dst)[q] = make_uint4(buf[4 * q], buf[4 * q + 1],
                                      buf[4 * q + 2], buf[4 * q + 3]);
}

// ---------------------------------------------------------------------------
// bf16-split mma.sync GEMM (unchanged from R6 — it worked).
#define RS 320
#define SMA_BYTES (128 * RS)
#define SM_TOTAL (2 * 128 * RS)   // 81920

template <bool RELU>
__global__ void __launch_bounds__(256, 2)
gemm_bf16_kernel(const float* __restrict__ X, int layer,
                 const float* __restrict__ bias,
                 float* __restrict__ out, int nN) {
    extern __shared__ char smem[];
    char* sA = smem;
    char* sB = smem + SMA_BYTES;

    const int tid = threadIdx.x;
    const int wid = tid >> 5;
    const int lane = tid & 31;
    const int g = lane >> 2;
    const int tg = lane & 3;
    const int warp_m = wid & 3;
    const int warp_n = wid >> 2;
    const int m0 = blockIdx.x * 128;
    const char* wbase = g_Wb + layer * 163840;

    float acc[2][8][4];
    #pragma unroll
    for (int t = 0; t < 2; t++)
        #pragma unroll
        for (int u = 0; u < 8; u++)
            #pragma unroll
            for (int c = 0; c < 4; c++) acc[t][u][c] = 0.f;

    #pragma unroll 1
    for (int kc = 0; kc < 4; kc++) {
        const float* asrc = (kc < 2) ? g_agg : X;
        const int koff = (kc & 1) * 64;
        if (kc > 0) __syncthreads();

        // ---- stage A ----
        #pragma unroll
        for (int it = 0; it < 2; it++) {
            int unit = tid + it * 256;
            int row = unit >> 2, ks = unit & 3;
            int node = m0 + row;
            float4 f0 = make_float4(0.f, 0.f, 0.f, 0.f), f1 = f0, f2 = f0, f3 = f0;
            if (node < nN) {
                const float4* s = (const float4*)(asrc + (size_t)node * 128 + koff + ks * 16);
                f0 = s[0]; f1 = s[1]; f2 = s[2]; f3 = s[3];
            }
            float v[16] = {f0.x, f0.y, f0.z, f0.w, f1.x, f1.y, f1.z, f1.w,
                           f2.x, f2.y, f2.z, f2.w, f3.x, f3.y, f3.z, f3.w};
            uint32_t buf[16];
            #pragma unroll
            for (int p = 0; p < 8; p++) {
                uint32_t hi2, lo2;
                split2_bf16(v[2 * p], v[2 * p + 1], hi2, lo2);
                int pos = 2 * (p & 3) + (p >> 2);
                buf[pos * 2] = hi2;
                buf[pos * 2 + 1] = lo2;
            }
            char* dst = sA + row * RS + ks * 64;
            #pragma unroll
            for (int q = 0; q < 4; q++)
                ((uint4*)dst)[q] = make_uint4(buf[4 * q], buf[4 * q + 1],
                                              buf[4 * q + 2], buf[4 * q + 3]);
        }
        // ---- stage B: flat copy of pre-split image ----
        {
            const uint4* src = (const uint4*)(wbase + kc * 40960);
            uint4* dst = (uint4*)sB;
            #pragma unroll
            for (int it = 0; it < 10; it++) {
                int idx = tid + it * 256;
                dst[idx] = src[idx];
            }
        }
        __syncthreads();

        // ---- MMA: 4 k-steps of 16 ----
        #pragma unroll
        for (int ks = 0; ks < 4; ks++) {
            uint32_t aH[2][4], aL[2][4];
            #pragma unroll
            for (int t = 0; t < 2; t++) {
                int r = warp_m * 32 + t * 16 + g;
                uint4 q0 = *(const uint4*)(sA + r * RS + ks * 64 + tg * 16);
                uint4 q1 = *(const uint4*)(sA + (r + 8) * RS + ks * 64 + tg * 16);
                aH[t][0] = q0.x; aH[t][1] = q1.x; aH[t][2] = q0.z; aH[t][3] = q1.z;
                aL[t][0] = q0.y; aL[t][1] = q1.y; aL[t][2] = q0.w; aL[t][3] = q1.w;
            }
            #pragma unroll
            for (int ug = 0; ug < 2; ug++) {
                #pragma unroll
                for (int uu = 0; uu < 4; uu++) {
                    int u = ug * 4 + uu;
                    int n = warp_n * 64 + u * 8 + g;
                    uint4 qb = *(const uint4*)(sB + n * RS + ks * 64 + tg * 16);
                    #pragma unroll
                    for (int t = 0; t < 2; t++) {
                        MMA_BF16(acc[t][u], aH[t][0], aH[t][1], aH[t][2], aH[t][3], qb.x, qb.z);
                        MMA_BF16(acc[t][u], aH[t][0], aH[t][1], aH[t][2], aH[t][3], qb.y, qb.w);
                        MMA_BF16(acc[t][u], aL[t][0], aL[t][1], aL[t][2], aL[t][3], qb.x, qb.z);
                    }
                }
            }
        }
    }

    // ---- epilogue ----
    #pragma unroll
    for (int u = 0; u < 8; u++) {
        int cb = warp_n * 64 + u * 8 + 2 * tg;
        float2 bv = *(const float2*)(bias + cb);
        #pragma unroll
        for (int t = 0; t < 2; t++) {
            int r0 = m0 + warp_m * 32 + t * 16 + g;
            float2 o0 = make_float2(acc[t][u][0] + bv.x, acc[t][u][1] + bv.y);
            float2 o1 = make_float2(acc[t][u][2] + bv.x, acc[t][u][3] + bv.y);
            if (RELU) {
                o0.x = fmaxf(o0.x, 0.f); o0.y = fmaxf(o0.y, 0.f);
                o1.x = fmaxf(o1.x, 0.f); o1.y = fmaxf(o1.y, 0.f);
            }
            if (r0 < nN)     *(float2*)(out + (size_t)r0 * 128 + cb) = o0;
            if (r0 + 8 < nN) *(float2*)(out + (size_t)(r0 + 8) * 128 + cb) = o1;
        }
    }
}

// ---------------------------------------------------------------------------
extern "C" void kernel_launch(void* const* d_in, const int* in_sizes, int n_in,
                              void* d_out, int out_size) {
    const float* x   = (const float*)d_in[0];
    const void*  eix = d_in[1];
    const float* Wl1 = (const float*)d_in[2];
    const float* Wr1 = (const float*)d_in[3];
    const float* b1  = (const float*)d_in[4];
    const float* Wl2 = (const float*)d_in[5];
    const float* Wr2 = (const float*)d_in[6];
    const float* b2  = (const float*)d_in[7];
    float* out = (float*)d_out;

    const int nN = in_sizes[0] / D;      // 100000
    const int nE = in_sizes[1] / 2;      // 1600000

    void *degp, *hp;
    cudaGetSymbolAddress(&degp, g_deg);
    cudaGetSymbolAddress(&hp,   g_h);
    float* h = (float*)hp;

    cudaFuncSetAttribute(gemm_bf16_kernel<true>,
                         cudaFuncAttributeMaxDynamicSharedMemorySize, SM_TOTAL);
    cudaFuncSetAttribute(gemm_bf16_kernel<false>,
                         cudaFuncAttributeMaxDynamicSharedMemorySize, SM_TOTAL);

    const int edgeBlocks = (nE + 255) / 256;
    const int aggBlocks  = (int)(((long long)nN * 32 + 255) / 256);
    const int gemmBlocks = (nN + 127) / 128;
    const int scanBlocks = (nN + 1023) / 1024;    // 98

    // ---- CSR build + weight pre-split (shared by both layers) ----
    cudaMemsetAsync(degp, 0, (size_t)nN * sizeof(int));
    detect_kernel<<<1, 1>>>(eix);
    wconv_kernel<<<16, 256>>>(Wl1, Wr1, Wl2, Wr2);
    deg_kernel<<<edgeBlocks, 256>>>(eix, nE);
    blocksum_kernel<<<scanBlocks, 256>>>(nN);
    scanpart_kernel<<<1, 128>>>(scanBlocks);
    offsets_kernel<<<scanBlocks, 256>>>(nN, nE);
    fill_kernel<<<edgeBlocks, 256>>>(eix, nE);

    // ---- layer 1 ----
    agg_kernel<<<aggBlocks, 256>>>((const float4*)x, nN);
    gemm_bf16_kernel<true><<<gemmBlocks, 256, SM_TOTAL>>>(x, 0, b1, h, nN);

    // ---- layer 2 ----
    agg_kernel<<<aggBlocks, 256>>>((const float4*)h, nN);
    gemm_bf16_kernel<false><<<gemmBlocks, 256, SM_TOTAL>>>(h, 1, b2, out, nN);
}

// round 8
// speedup vs baseline: 2.0061x; 1.0157x over previous
#include <cuda_runtime.h>
#include <cuda_bf16.h>
#include <cstdint>

#define NMAX 100000
#define D 128

typedef unsigned long long ull;

// Scratch (device globals: allocation-free per harness rules)
__device__ __align__(256) float g_agg[(size_t)NMAX * D];   // mean-aggregated features
__device__ __align__(256) float g_h[(size_t)NMAX * D];     // layer-1 output
__device__ __align__(16)  char  g_Wb[327680];              // pre-split weights (bf16 hi/lo)
__device__ int   g_deg[NMAX];
__device__ int   g_off[NMAX + 1];
__device__ int   g_cur[NMAX];
__device__ int   g_esrc[1600000 + 1024];                   // src sorted by dst (CSR)
__device__ float g_inv[NMAX];
__device__ int   g_part[256];
__device__ int   g_pbase[256];
__device__ int   g_idx32;

// ---------------------------------------------------------------------------
__device__ __forceinline__ uint32_t smem_u32(const void* p) {
    uint32_t a;
    asm("{ .reg .u64 t; cvta.to.shared.u64 t, %1; cvt.u32.u64 %0, t; }" : "=r"(a) : "l"(p));
    return a;
}

__device__ __forceinline__ void cpasync16(uint32_t s, const void* g, int sz) {
    asm volatile("cp.async.cg.shared.global [%0], [%1], 16, %2;"
                 :: "r"(s), "l"(g), "r"(sz) : "memory");
}

// Split fp32 into two bf16 (hi + lo), packed as bf16x2 pairs for (v0, v1).
__device__ __forceinline__ void split2_bf16(float v0, float v1,
                                            uint32_t& hi2, uint32_t& lo2) {
    asm("cvt.rn.bf16x2.f32 %0, %1, %2;" : "=r"(hi2) : "f"(v1), "f"(v0));
    float h0 = __uint_as_float(hi2 << 16);
    float h1 = __uint_as_float(hi2 & 0xffff0000u);
    float l0 = v0 - h0, l1 = v1 - h1;
    asm("cvt.rn.bf16x2.f32 %0, %1, %2;" : "=r"(lo2) : "f"(l1), "f"(l0));
}

#define MMA_BF16(c, a0, a1, a2, a3, b0, b1)                                   \
    asm volatile("mma.sync.aligned.m16n8k16.row.col.f32.bf16.bf16.f32 "       \
                 "{%0,%1,%2,%3},{%4,%5,%6,%7},{%8,%9},{%0,%1,%2,%3};"         \
                 : "+f"((c)[0]), "+f"((c)[1]), "+f"((c)[2]), "+f"((c)[3])     \
                 : "r"(a0), "r"(a1), "r"(a2), "r"(a3), "r"(b0), "r"(b1))

// ---------------------------------------------------------------------------
__global__ void detect_kernel(const void* eidx) {
    const ull* p = (const ull*)eidx;
    int is32 = 0;
    #pragma unroll
    for (int i = 0; i < 4; i++)
        if (p[i] >= (1ULL << 32)) is32 = 1;
    g_idx32 = is32;
}

__device__ __forceinline__ int load_idx(const void* eidx, long long pos) {
    if (g_idx32) return ((const int*)eidx)[pos];
    return (int)(((const long long*)eidx)[pos]);
}

// 4 edges per thread, vectorized index loads (4x MLP on latency-bound pass).
__global__ void deg_kernel(const void* eidx, int nE) {
    int t = blockIdx.x * blockDim.x + threadIdx.x;
    int ngrp = nE >> 2;
    if (t < ngrp) {
        int d0, d1, d2, d3;
        if (g_idx32) {
            int4 v = ((const int4*)eidx)[ngrp + t];   // dst base = nE ints
            d0 = v.x; d1 = v.y; d2 = v.z; d3 = v.w;
        } else {
            longlong2 v0 = ((const longlong2*)eidx)[(nE >> 1) + t * 2];
            longlong2 v1 = ((const longlong2*)eidx)[(nE >> 1) + t * 2 + 1];
            d0 = (int)v0.x; d1 = (int)v0.y; d2 = (int)v1.x; d3 = (int)v1.y;
        }
        atomicAdd(&g_deg[d0], 1);
        atomicAdd(&g_deg[d1], 1);
        atomicAdd(&g_deg[d2], 1);
        atomicAdd(&g_deg[d3], 1);
    } else if (t == ngrp) {
        for (int e = ngrp * 4; e < nE; e++)
            atomicAdd(&g_deg[load_idx(eidx, (long long)nE + e)], 1);
    }
}

// ---------------------------------------------------------------------------
// Parallel 3-phase exclusive scan over degrees.
__global__ void blocksum_kernel(int nN) {
    __shared__ int ws[8];
    int t = threadIdx.x;
    int base = blockIdx.x * 1024 + t * 4;
    int s = 0;
    #pragma unroll
    for (int j = 0; j < 4; j++) {
        int i = base + j;
        if (i < nN) s += g_deg[i];
    }
    #pragma unroll
    for (int o = 16; o > 0; o >>= 1) s += __shfl_down_sync(~0u, s, o);
    if ((t & 31) == 0) ws[t >> 5] = s;
    __syncthreads();
    if (t < 8) {
        int v = ws[t];
        #pragma unroll
        for (int o = 4; o > 0; o >>= 1) v += __shfl_down_sync(0xff, v, o);
        if (t == 0) g_part[blockIdx.x] = v;
    }
}

__global__ void scanpart_kernel(int nb) {
    __shared__ int sm[128];
    int t = threadIdx.x;
    int v = (t < nb) ? g_part[t] : 0;
    sm[t] = v;
    __syncthreads();
    for (int o = 1; o < 128; o <<= 1) {
        int u = (t >= o) ? sm[t - o] : 0;
        __syncthreads();
        sm[t] += u;
        __syncthreads();
    }
    g_pbase[t] = (t == 0) ? 0 : sm[t - 1];
}

__global__ void offsets_kernel(int nN, int nE) {
    __shared__ int warp_tot[8];
    int t = threadIdx.x;
    int blk = blockIdx.x;
    int lane = t & 31, w = t >> 5;
    int base = blk * 1024 + t * 4;
    int d[4];
    int s = 0;
    #pragma unroll
    for (int j = 0; j < 4; j++) {
        int i = base + j;
        d[j] = (i < nN) ? g_deg[i] : 0;
        s += d[j];
    }
    int inc = s;
    #pragma unroll
    for (int o = 1; o < 32; o <<= 1) {
        int u = __shfl_up_sync(~0u, inc, o);
        if (lane >= o) inc += u;
    }
    if (lane == 31) warp_tot[w] = inc;
    __syncthreads();
    if (t < 8) {
        int v = warp_tot[t];
        #pragma unroll
        for (int o = 1; o < 8; o <<= 1) {
            int u = __shfl_up_sync(0xff, v, o);
            if (t >= o) v += u;
        }
        warp_tot[t] = v;
    }
    __syncthreads();
    int run = g_pbase[blk] + (inc - s) + ((w > 0) ? warp_tot[w - 1] : 0);
    #pragma unroll
    for (int j = 0; j < 4; j++) {
        int i = base + j;
        if (i < nN) {
            g_off[i] = run;
            g_cur[i] = run;
            g_inv[i] = 1.0f / (float)(d[j] > 0 ? d[j] : 1);
            run += d[j];
        }
    }
    if (blk == 0 && t == 0) g_off[nN] = nE;
}

// 4 edges per thread, vectorized.
__global__ void fill_kernel(const void* eidx, int nE) {
    int t = blockIdx.x * blockDim.x + threadIdx.x;
    int ngrp = nE >> 2;
    if (t < ngrp) {
        int s0, s1, s2, s3, d0, d1, d2, d3;
        if (g_idx32) {
            int4 sv = ((const int4*)eidx)[t];
            int4 dv = ((const int4*)eidx)[ngrp + t];
            s0 = sv.x; s1 = sv.y; s2 = sv.z; s3 = sv.w;
            d0 = dv.x; d1 = dv.y; d2 = dv.z; d3 = dv.w;
        } else {
            longlong2 a0 = ((const longlong2*)eidx)[t * 2];
            longlong2 a1 = ((const longlong2*)eidx)[t * 2 + 1];
            longlong2 b0 = ((const longlong2*)eidx)[(nE >> 1) + t * 2];
            longlong2 b1 = ((const longlong2*)eidx)[(nE >> 1) + t * 2 + 1];
            s0 = (int)a0.x; s1 = (int)a0.y; s2 = (int)a1.x; s3 = (int)a1.y;
            d0 = (int)b0.x; d1 = (int)b0.y; d2 = (int)b1.x; d3 = (int)b1.y;
        }
        g_esrc[atomicAdd(&g_cur[d0], 1)] = s0;
        g_esrc[atomicAdd(&g_cur[d1], 1)] = s1;
        g_esrc[atomicAdd(&g_cur[d2], 1)] = s2;
        g_esrc[atomicAdd(&g_cur[d3], 1)] = s3;
    } else if (t == ngrp) {
        for (int e = ngrp * 4; e < nE; e++) {
            int src = load_idx(eidx, e);
            int dst = load_idx(eidx, (long long)nE + e);
            g_esrc[atomicAdd(&g_cur[dst], 1)] = src;
        }
    }
}

// ---------------------------------------------------------------------------
// Gather aggregation: one warp per node, lane handles one float4. 4-wide MLP.
__global__ void agg_kernel(const float4* __restrict__ feat, int nN) {
    int gtid = blockIdx.x * blockDim.x + threadIdx.x;
    int w = gtid >> 5;
    int lane = gtid & 31;
    if (w >= nN) return;
    int beg = g_off[w], end = g_off[w + 1];
    float4 a0 = make_float4(0.f, 0.f, 0.f, 0.f);
    float4 a1 = a0;
    int i = beg;
    for (; i + 3 < end; i += 4) {
        int s0 = g_esrc[i], s1 = g_esrc[i + 1];
        int s2 = g_esrc[i + 2], s3 = g_esrc[i + 3];
        float4 v0 = feat[(size_t)s0 * 32 + lane];
        float4 v1 = feat[(size_t)s1 * 32 + lane];
        float4 v2 = feat[(size_t)s2 * 32 + lane];
        float4 v3 = feat[(size_t)s3 * 32 + lane];
        a0.x += v0.x; a0.y += v0.y; a0.z += v0.z; a0.w += v0.w;
        a1.x += v1.x; a1.y += v1.y; a1.z += v1.z; a1.w += v1.w;
        a0.x += v2.x; a0.y += v2.y; a0.z += v2.z; a0.w += v2.w;
        a1.x += v3.x; a1.y += v3.y; a1.z += v3.z; a1.w += v3.w;
    }
    for (; i < end; i++) {
        int s0 = g_esrc[i];
        float4 v0 = feat[(size_t)s0 * 32 + lane];
        a0.x += v0.x; a0.y += v0.y; a0.z += v0.z; a0.w += v0.w;
    }
    float inv = g_inv[w];
    float4 o = make_float4((a0.x + a1.x) * inv, (a0.y + a1.y) * inv,
                           (a0.z + a1.z) * inv, (a0.w + a1.w) * inv);
    ((float4*)g_agg)[(size_t)w * 32 + lane] = o;
}

// ---------------------------------------------------------------------------
// Pre-split weights into the staged-B image (read directly by GEMM via LDG).
__global__ void wconv_kernel(const float* __restrict__ Wl1, const float* __restrict__ Wr1,
                             const float* __restrict__ Wl2, const float* __restrict__ Wr2) {
    int unit = blockIdx.x * 256 + threadIdx.x;   // 4096 units
    if (unit >= 4096) return;
    int layer = unit >> 11;
    int rem = unit & 2047;
    int kc = rem >> 9;
    int rem2 = rem & 511;
    int n = rem2 >> 2;
    int ks = rem2 & 3;
    const float* Wsrc = (layer == 0) ? ((kc < 2) ? Wl1 : Wr1)
                                     : ((kc < 2) ? Wl2 : Wr2);
    int kbase = (kc & 1) * 64 + ks * 16;
    char* dst = g_Wb + layer * 163840 + kc * 40960 + n * 320 + ks * 64;
    uint32_t buf[16];
    #pragma unroll
    for (int p = 0; p < 8; p++) {
        float v0 = Wsrc[(kbase + 2 * p) * 128 + n];      // B[n][k] = W[k][n]
        float v1 = Wsrc[(kbase + 2 * p + 1) * 128 + n];
        uint32_t hi2, lo2;
        split2_bf16(v0, v1, hi2, lo2);
        int pos = 2 * (p & 3) + (p >> 2);
        buf[pos * 2] = hi2;
        buf[pos * 2 + 1] = lo2;
    }
    #pragma unroll
    for (int q = 0; q < 4; q++)
        ((uint4*)dst)[q] = make_uint4(buf[4 * q], buf[4 * q + 1],
                                      buf[4 * q + 2], buf[4 * q + 3]);
}

// ---------------------------------------------------------------------------
// bf16-split mma.sync GEMM, pipelined:
//  - raw A floats prefetched via cp.async one chunk ahead (per-thread regions)
//  - A image (bf16 hi/lo) converted raw->img between chunks
//  - B fragments read directly from g_Wb via __ldg (L1/L2-hot; no B staging)
#define RSI 304
#define IMG_BYTES (128 * RSI)          // 38912
#define SM_TOTAL (2 * IMG_BYTES)       // 77824 (img + raw), 2 CTAs/SM

template <bool RELU>
__global__ void __launch_bounds__(256, 2)
gemm_bf16_kernel(const float* __restrict__ X, int layer,
                 const float* __restrict__ bias,
                 float* __restrict__ out, int nN) {
    extern __shared__ char smem[];
    char* img = smem;
    char* raw = smem + IMG_BYTES;
    const uint32_t raw_u = smem_u32(raw);

    const int tid = threadIdx.x;
    const int wid = tid >> 5;
    const int lane = tid & 31;
    const int g = lane >> 2;
    const int tg = lane & 3;
    const int warp_m = wid & 3;
    const int warp_n = wid >> 2;
    const int m0 = blockIdx.x * 128;
    const char* wbase = g_Wb + layer * 163840;

    // prefetch raw A for chunk kc (per-thread region; zero-fill OOB rows)
    auto stageA = [&](int kc) {
        const float* asrc = (kc < 2) ? g_agg : X;
        const int koff = (kc & 1) * 64;
        #pragma unroll
        for (int it = 0; it < 2; it++) {
            int u = tid + it * 256;
            int row = u >> 2, ks = u & 3;
            int node = m0 + row;
            const char* gp = (const char*)(asrc + (size_t)node * 128 + koff + ks * 16);
            uint32_t sp = raw_u + row * RSI + ks * 64;
            int sz = (node < nN) ? 16 : 0;
            #pragma unroll
            for (int q = 0; q < 4; q++)
                cpasync16(sp + q * 16, gp + q * 16, sz);
        }
        asm volatile("cp.async.commit_group;" ::: "memory");
    };

    // convert raw floats -> bf16 hi/lo image (same per-thread region)
    auto cvtA = [&]() {
        #pragma unroll
        for (int it = 0; it < 2; it++) {
            int u = tid + it * 256;
            int row = u >> 2, ks = u & 3;
            const char* rp = raw + row * RSI + ks * 64;
            float4 f0 = *(const float4*)(rp);
            float4 f1 = *(const float4*)(rp + 16);
            float4 f2 = *(const float4*)(rp + 32);
            float4 f3 = *(const float4*)(rp + 48);
            float v[16] = {f0.x, f0.y, f0.z, f0.w, f1.x, f1.y, f1.z, f1.w,
                           f2.x, f2.y, f2.z, f2.w, f3.x, f3.y, f3.z, f3.w};
            uint32_t buf[16];
            #pragma unroll
            for (int p = 0; p < 8; p++) {
                uint32_t hi2, lo2;
                split2_bf16(v[2 * p], v[2 * p + 1], hi2, lo2);
                int pos = 2 * (p & 3) + (p >> 2);
                buf[pos * 2] = hi2;
                buf[pos * 2 + 1] = lo2;
            }
            char* dst = img + row * RSI + ks * 64;
            #pragma unroll
            for (int q = 0; q < 4; q++)
                ((uint4*)dst)[q] = make_uint4(buf[4 * q], buf[4 * q + 1],
                                              buf[4 * q + 2], buf[4 * q + 3]);
        }
    };

    float acc[2][8][4];
    #pragma unroll
    for (int t = 0; t < 2; t++)
        #pragma unroll
        for (int u = 0; u < 8; u++)
            #pragma unroll
            for (int c = 0; c < 4; c++) acc[t][u][c] = 0.f;

    // prologue
    stageA(0);
    asm volatile("cp.async.wait_group 0;" ::: "memory");
    cvtA();
    stageA(1);
    __syncthreads();

    #pragma unroll 1
    for (int kc = 0; kc < 4; kc++) {
        const char* wkc = wbase + kc * 40960;
        // ---- MMA: 4 k-steps of 16; B direct from gmem ----
        #pragma unroll
        for (int ks = 0; ks < 4; ks++) {
            // first half of B fragments
            uint4 qbA[4];
            #pragma unroll
            for (int uu = 0; uu < 4; uu++) {
                int n = warp_n * 64 + uu * 8 + g;
                qbA[uu] = __ldg((const uint4*)(wkc + n * 320 + ks * 64 + tg * 16));
            }
            // A fragments
            uint32_t aH[2][4], aL[2][4];
            #pragma unroll
            for (int t = 0; t < 2; t++) {
                int r = warp_m * 32 + t * 16 + g;
                uint4 q0 = *(const uint4*)(img + r * RSI + ks * 64 + tg * 16);
                uint4 q1 = *(const uint4*)(img + (r + 8) * RSI + ks * 64 + tg * 16);
                aH[t][0] = q0.x; aH[t][1] = q1.x; aH[t][2] = q0.z; aH[t][3] = q1.z;
                aL[t][0] = q0.y; aL[t][1] = q1.y; aL[t][2] = q0.w; aL[t][3] = q1.w;
            }
            // second half of B fragments (loads overlap first-half MMAs below)
            uint4 qbB[4];
            #pragma unroll
            for (int uu = 0; uu < 4; uu++) {
                int n = warp_n * 64 + (uu + 4) * 8 + g;
                qbB[uu] = __ldg((const uint4*)(wkc + n * 320 + ks * 64 + tg * 16));
            }
            #pragma unroll
            for (int uu = 0; uu < 4; uu++) {
                #pragma unroll
                for (int t = 0; t < 2; t++) {
                    MMA_BF16(acc[t][uu], aH[t][0], aH[t][1], aH[t][2], aH[t][3], qbA[uu].x, qbA[uu].z);
                    MMA_BF16(acc[t][uu], aH[t][0], aH[t][1], aH[t][2], aH[t][3], qbA[uu].y, qbA[uu].w);
                    MMA_BF16(acc[t][uu], aL[t][0], aL[t][1], aL[t][2], aL[t][3], qbA[uu].x, qbA[uu].z);
                }
            }
            #pragma unroll
            for (int uu = 0; uu < 4; uu++) {
                #pragma unroll
                for (int t = 0; t < 2; t++) {
                    MMA_BF16(acc[t][uu + 4], aH[t][0], aH[t][1], aH[t][2], aH[t][3], qbB[uu].x, qbB[uu].z);
                    MMA_BF16(acc[t][uu + 4], aH[t][0], aH[t][1], aH[t][2], aH[t][3], qbB[uu].y, qbB[uu].w);
                    MMA_BF16(acc[t][uu + 4], aL[t][0], aL[t][1], aL[t][2], aL[t][3], qbB[uu].x, qbB[uu].z);
                }
            }
        }
        // ---- rotate pipeline ----
        if (kc < 3) {
            asm volatile("cp.async.wait_group 0;" ::: "memory");
            __syncthreads();                 // all warps done reading img(kc)
            cvtA();                          // raw(kc+1) -> img
            if (kc < 2) stageA(kc + 2);
            __syncthreads();                 // img(kc+1) visible
        }
    }

    // ---- epilogue ----
    #pragma unroll
    for (int u = 0; u < 8; u++) {
        int cb = warp_n * 64 + u * 8 + 2 * tg;
        float2 bv = *(const float2*)(bias + cb);
        #pragma unroll
        for (int t = 0; t < 2; t++) {
            int r0 = m0 + warp_m * 32 + t * 16 + g;
            float2 o0 = make_float2(acc[t][u][0] + bv.x, acc[t][u][1] + bv.y);
            float2 o1 = make_float2(acc[t][u][2] + bv.x, acc[t][u][3] + bv.y);
            if (RELU) {
                o0.x = fmaxf(o0.x, 0.f); o0.y = fmaxf(o0.y, 0.f);
                o1.x = fmaxf(o1.x, 0.f); o1.y = fmaxf(o1.y, 0.f);
            }
            if (r0 < nN)     *(float2*)(out + (size_t)r0 * 128 + cb) = o0;
            if (r0 + 8 < nN) *(float2*)(out + (size_t)(r0 + 8) * 128 + cb) = o1;
        }
    }
}

// ---------------------------------------------------------------------------
extern "C" void kernel_launch(void* const* d_in, const int* in_sizes, int n_in,
                              void* d_out, int out_size) {
    const float* x   = (const float*)d_in[0];
    const void*  eix = d_in[1];
    const float* Wl1 = (const float*)d_in[2];
    const float* Wr1 = (const float*)d_in[3];
    const float* b1  = (const float*)d_in[4];
    const float* Wl2 = (const float*)d_in[5];
    const float* Wr2 = (const float*)d_in[6];
    const float* b2  = (const float*)d_in[7];
    float* out = (float*)d_out;

    const int nN = in_sizes[0] / D;      // 100000
    const int nE = in_sizes[1] / 2;      // 1600000

    void *degp, *hp;
    cudaGetSymbolAddress(&degp, g_deg);
    cudaGetSymbolAddress(&hp,   g_h);
    float* h = (float*)hp;

    cudaFuncSetAttribute(gemm_bf16_kernel<true>,
                         cudaFuncAttributeMaxDynamicSharedMemorySize, SM_TOTAL);
    cudaFuncSetAttribute(gemm_bf16_kernel<false>,
                         cudaFuncAttributeMaxDynamicSharedMemorySize, SM_TOTAL);

    const int edgeGrpBlocks = ((nE / 4 + 1) + 255) / 256;
    const int aggBlocks  = (int)(((long long)nN * 32 + 255) / 256);
    const int gemmBlocks = (nN + 127) / 128;
    const int scanBlocks = (nN + 1023) / 1024;    // 98

    // ---- CSR build + weight pre-split (shared by both layers) ----
    cudaMemsetAsync(degp, 0, (size_t)nN * sizeof(int));
    detect_kernel<<<1, 1>>>(eix);
    wconv_kernel<<<16, 256>>>(Wl1, Wr1, Wl2, Wr2);
    deg_kernel<<<edgeGrpBlocks, 256>>>(eix, nE);
    blocksum_kernel<<<scanBlocks, 256>>>(nN);
    scanpart_kernel<<<1, 128>>>(scanBlocks);
    offsets_kernel<<<scanBlocks, 256>>>(nN, nE);
    fill_kernel<<<edgeGrpBlocks, 256>>>(eix, nE);

    // ---- layer 1 ----
    agg_kernel<<<aggBlocks, 256>>>((const float4*)x, nN);
    gemm_bf16_kernel<true><<<gemmBlocks, 256, SM_TOTAL>>>(x, 0, b1, h, nN);

    // ---- layer 2 ----
    agg_kernel<<<aggBlocks, 256>>>((const float4*)h, nN);
    gemm_bf16_kernel<false><<<gemmBlocks, 256, SM_TOTAL>>>(h, 1, b2, out, nN);
}

// round 10
// speedup vs baseline: 2.1083x; 1.0509x over previous
#include <cuda_runtime.h>
#include <cuda_bf16.h>
#include <cuda_fp16.h>
#include <cstdint>

#define NMAX 100000
#define D 128

typedef unsigned long long ull;

// Scratch (device globals: allocation-free per harness rules)
__device__ __align__(256) float g_agg[(size_t)NMAX * D];   // mean-aggregated features
__device__ __align__(256) float g_h[(size_t)NMAX * D];     // layer-1 output (fp32)
__device__ __align__(256) uint2 g_x16[(size_t)NMAX * 32];  // fp16 plane of x
__device__ __align__(256) uint2 g_h16[(size_t)NMAX * 32];  // fp16 plane of h
__device__ __align__(16)  char  g_Wb[327680];              // pre-split weights (bf16 hi/lo)
__device__ int   g_deg[NMAX];
__device__ int   g_off[NMAX + 1];
__device__ int   g_cur[NMAX];
__device__ int   g_esrc[1600000 + 1024];                   // src sorted by dst (CSR)
__device__ float g_inv[NMAX];
__device__ int   g_part[256];
__device__ int   g_pbase[256];
__device__ int   g_idx32;

// ---------------------------------------------------------------------------
__device__ __forceinline__ uint32_t smem_u32(const void* p) {
    uint32_t a;
    asm("{ .reg .u64 t; cvta.to.shared.u64 t, %1; cvt.u32.u64 %0, t; }" : "=r"(a) : "l"(p));
    return a;
}

__device__ __forceinline__ void cpasync16(uint32_t s, const void* g, int sz) {
    asm volatile("cp.async.cg.shared.global [%0], [%1], 16, %2;"
                 :: "r"(s), "l"(g), "r"(sz) : "memory");
}

// Split fp32 into two bf16 (hi + lo), packed as bf16x2 pairs for (v0, v1).
__device__ __forceinline__ void split2_bf16(float v0, float v1,
                                            uint32_t& hi2, uint32_t& lo2) {
    asm("cvt.rn.bf16x2.f32 %0, %1, %2;" : "=r"(hi2) : "f"(v1), "f"(v0));
    float h0 = __uint_as_float(hi2 << 16);
    float h1 = __uint_as_float(hi2 & 0xffff0000u);
    float l0 = v0 - h0, l1 = v1 - h1;
    asm("cvt.rn.bf16x2.f32 %0, %1, %2;" : "=r"(lo2) : "f"(l1), "f"(l0));
}

#define MMA_BF16(c, a0, a1, a2, a3, b0, b1)                                   \
    asm volatile("mma.sync.aligned.m16n8k16.row.col.f32.bf16.bf16.f32 "       \
                 "{%0,%1,%2,%3},{%4,%5,%6,%7},{%8,%9},{%0,%1,%2,%3};"         \
                 : "+f"((c)[0]), "+f"((c)[1]), "+f"((c)[2]), "+f"((c)[3])     \
                 : "r"(a0), "r"(a1), "r"(a2), "r"(a3), "r"(b0), "r"(b1))

// ---------------------------------------------------------------------------
__global__ void detect_kernel(const void* eidx) {
    const ull* p = (const ull*)eidx;
    int is32 = 0;
    #pragma unroll
    for (int i = 0; i < 4; i++)
        if (p[i] >= (1ULL << 32)) is32 = 1;
    g_idx32 = is32;
}

__device__ __forceinline__ int load_idx(const void* eidx, long long pos) {
    if (g_idx32) return ((const int*)eidx)[pos];
    return (int)(((const long long*)eidx)[pos]);
}

// fp32 -> fp16 plane conversion: one float4 -> one uint2 per thread.
__global__ void tohalf_kernel(const float4* __restrict__ src,
                              uint2* __restrict__ dst, int n4) {
    int t = blockIdx.x * blockDim.x + threadIdx.x;
    if (t >= n4) return;
    float4 v = src[t];
    __half2 h0 = __floats2half2_rn(v.x, v.y);
    __half2 h1 = __floats2half2_rn(v.z, v.w);
    dst[t] = make_uint2(*(uint32_t*)&h0, *(uint32_t*)&h1);
}

// 4 edges per thread, vectorized index loads.
__global__ void deg_kernel(const void* eidx, int nE) {
    int t = blockIdx.x * blockDim.x + threadIdx.x;
    int ngrp = nE >> 2;
    if (t < ngrp) {
        int d0, d1, d2, d3;
        if (g_idx32) {
            int4 v = ((const int4*)eidx)[ngrp + t];
            d0 = v.x; d1 = v.y; d2 = v.z; d3 = v.w;
        } else {
            longlong2 v0 = ((const longlong2*)eidx)[(nE >> 1) + t * 2];
            longlong2 v1 = ((const longlong2*)eidx)[(nE >> 1) + t * 2 + 1];
            d0 = (int)v0.x; d1 = (int)v0.y; d2 = (int)v1.x; d3 = (int)v1.y;
        }
        atomicAdd(&g_deg[d0], 1);
        atomicAdd(&g_deg[d1], 1);
        atomicAdd(&g_deg[d2], 1);
        atomicAdd(&g_deg[d3], 1);
    } else if (t == ngrp) {
        for (int e = ngrp * 4; e < nE; e++)
            atomicAdd(&g_deg[load_idx(eidx, (long long)nE + e)], 1);
    }
}

// ---------------------------------------------------------------------------
// Parallel 3-phase exclusive scan over degrees.
__global__ void blocksum_kernel(int nN) {
    __shared__ int ws[8];
    int t = threadIdx.x;
    int base = blockIdx.x * 1024 + t * 4;
    int s = 0;
    #pragma unroll
    for (int j = 0; j < 4; j++) {
        int i = base + j;
        if (i < nN) s += g_deg[i];
    }
    #pragma unroll
    for (int o = 16; o > 0; o >>= 1) s += __shfl_down_sync(~0u, s, o);
    if ((t & 31) == 0) ws[t >> 5] = s;
    __syncthreads();
    if (t < 8) {
        int v = ws[t];
        #pragma unroll
        for (int o = 4; o > 0; o >>= 1) v += __shfl_down_sync(0xff, v, o);
        if (t == 0) g_part[blockIdx.x] = v;
    }
}

__global__ void scanpart_kernel(int nb) {
    __shared__ int sm[128];
    int t = threadIdx.x;
    int v = (t < nb) ? g_part[t] : 0;
    sm[t] = v;
    __syncthreads();
    for (int o = 1; o < 128; o <<= 1) {
        int u = (t >= o) ? sm[t - o] : 0;
        __syncthreads();
        sm[t] += u;
        __syncthreads();
    }
    g_pbase[t] = (t == 0) ? 0 : sm[t - 1];
}

__global__ void offsets_kernel(int nN, int nE) {
    __shared__ int warp_tot[8];
    int t = threadIdx.x;
    int blk = blockIdx.x;
    int lane = t & 31, w = t >> 5;
    int base = blk * 1024 + t * 4;
    int d[4];
    int s = 0;
    #pragma unroll
    for (int j = 0; j < 4; j++) {
        int i = base + j;
        d[j] = (i < nN) ? g_deg[i] : 0;
        s += d[j];
    }
    int inc = s;
    #pragma unroll
    for (int o = 1; o < 32; o <<= 1) {
        int u = __shfl_up_sync(~0u, inc, o);
        if (lane >= o) inc += u;
    }
    if (lane == 31) warp_tot[w] = inc;
    __syncthreads();
    if (t < 8) {
        int v = warp_tot[t];
        #pragma unroll
        for (int o = 1; o < 8; o <<= 1) {
            int u = __shfl_up_sync(0xff, v, o);
            if (t >= o) v += u;
        }
        warp_tot[t] = v;
    }
    __syncthreads();
    int run = g_pbase[blk] + (inc - s) + ((w > 0) ? warp_tot[w - 1] : 0);
    #pragma unroll
    for (int j = 0; j < 4; j++) {
        int i = base + j;
        if (i < nN) {
            g_off[i] = run;
            g_cur[i] = run;
            g_inv[i] = 1.0f / (float)(d[j] > 0 ? d[j] : 1);
            run += d[j];
        }
    }
    if (blk == 0 && t == 0) g_off[nN] = nE;
}

// 4 edges per thread, vectorized.
__global__ void fill_kernel(const void* eidx, int nE) {
    int t = blockIdx.x * blockDim.x + threadIdx.x;
    int ngrp = nE >> 2;
    if (t < ngrp) {
        int s0, s1, s2, s3, d0, d1, d2, d3;
        if (g_idx32) {
            int4 sv = ((const int4*)eidx)[t];
            int4 dv = ((const int4*)eidx)[ngrp + t];
            s0 = sv.x; s1 = sv.y; s2 = sv.z; s3 = sv.w;
            d0 = dv.x; d1 = dv.y; d2 = dv.z; d3 = dv.w;
        } else {
            longlong2 a0 = ((const longlong2*)eidx)[t * 2];
            longlong2 a1 = ((const longlong2*)eidx)[t * 2 + 1];
            longlong2 b0 = ((const longlong2*)eidx)[(nE >> 1) + t * 2];
            longlong2 b1 = ((const longlong2*)eidx)[(nE >> 1) + t * 2 + 1];
            s0 = (int)a0.x; s1 = (int)a0.y; s2 = (int)a1.x; s3 = (int)a1.y;
            d0 = (int)b0.x; d1 = (int)b0.y; d2 = (int)b1.x; d3 = (int)b1.y;
        }
        g_esrc[atomicAdd(&g_cur[d0], 1)] = s0;
        g_esrc[atomicAdd(&g_cur[d1], 1)] = s1;
        g_esrc[atomicAdd(&g_cur[d2], 1)] = s2;
        g_esrc[atomicAdd(&g_cur[d3], 1)] = s3;
    } else if (t == ngrp) {
        for (int e = ngrp * 4; e < nE; e++) {
            int src = load_idx(eidx, e);
            int dst = load_idx(eidx, (long long)nE + e);
            g_esrc[atomicAdd(&g_cur[dst], 1)] = src;
        }
    }
}

// ---------------------------------------------------------------------------
// fp16-plane gather aggregation: warp per node, lane loads uint2 (4 halves).
// Accumulates fp32, writes fp32 mean. Halves the L2 gather traffic.
__device__ __forceinline__ void acc4h(float4& a, uint2 v) {
    float2 p = __half22float2(*(__half2*)&v.x);
    float2 q = __half22float2(*(__half2*)&v.y);
    a.x += p.x; a.y += p.y; a.z += q.x; a.w += q.y;
}

__global__ void agg16_kernel(const uint2* __restrict__ f16, int nN) {
    int gtid = blockIdx.x * blockDim.x + threadIdx.x;
    int w = gtid >> 5;
    int lane = gtid & 31;
    if (w >= nN) return;
    int beg = g_off[w], end = g_off[w + 1];
    float4 a0 = make_float4(0.f, 0.f, 0.f, 0.f);
    float4 a1 = a0;
    int i = beg;
    for (; i + 3 < end; i += 4) {
        int s0 = g_esrc[i], s1 = g_esrc[i + 1];
        int s2 = g_esrc[i + 2], s3 = g_esrc[i + 3];
        uint2 v0 = f16[(size_t)s0 * 32 + lane];
        uint2 v1 = f16[(size_t)s1 * 32 + lane];
        uint2 v2 = f16[(size_t)s2 * 32 + lane];
        uint2 v3 = f16[(size_t)s3 * 32 + lane];
        acc4h(a0, v0); acc4h(a1, v1); acc4h(a0, v2); acc4h(a1, v3);
    }
    for (; i < end; i++) {
        uint2 v0 = f16[(size_t)g_esrc[i] * 32 + lane];
        acc4h(a0, v0);
    }
    float inv = g_inv[w];
    float4 o = make_float4((a0.x + a1.x) * inv, (a0.y + a1.y) * inv,
                           (a0.z + a1.z) * inv, (a0.w + a1.w) * inv);
    ((float4*)g_agg)[(size_t)w * 32 + lane] = o;
}

// ---------------------------------------------------------------------------
// Pre-split weights into the staged-B image (read directly by GEMM via LDG).
__global__ void wconv_kernel(const float* __restrict__ Wl1, const float* __restrict__ Wr1,
                             const float* __restrict__ Wl2, const float* __restrict__ Wr2) {
    int unit = blockIdx.x * 256 + threadIdx.x;   // 4096 units
    if (unit >= 4096) return;
    int layer = unit >> 11;
    int rem = unit & 2047;
    int kc = rem >> 9;
    int rem2 = rem & 511;
    int n = rem2 >> 2;
    int ks = rem2 & 3;
    const float* Wsrc = (layer == 0) ? ((kc < 2) ? Wl1 : Wr1)
                                     : ((kc < 2) ? Wl2 : Wr2);
    int kbase = (kc & 1) * 64 + ks * 16;
    char* dst = g_Wb + layer * 163840 + kc * 40960 + n * 320 + ks * 64;
    uint32_t buf[16];
    #pragma unroll
    for (int p = 0; p < 8; p++) {
        float v0 = Wsrc[(kbase + 2 * p) * 128 + n];      // B[n][k] = W[k][n]
        float v1 = Wsrc[(kbase + 2 * p + 1) * 128 + n];
        uint32_t hi2, lo2;
        split2_bf16(v0, v1, hi2, lo2);
        int pos = 2 * (p & 3) + (p >> 2);
        buf[pos * 2] = hi2;
        buf[pos * 2 + 1] = lo2;
    }
    #pragma unroll
    for (int q = 0; q < 4; q++)
        ((uint4*)dst)[q] = make_uint4(buf[4 * q], buf[4 * q + 1],
                                      buf[4 * q + 2], buf[4 * q + 3]);
}

// ---------------------------------------------------------------------------
// bf16-split mma.sync GEMM (R8 structure). Epilogue optionally also writes the
// fp16 plane of the output (out16 != nullptr) for the next layer's gather.
#define RSI 304
#define IMG_BYTES (128 * RSI)          // 38912
#define SM_TOTAL (2 * IMG_BYTES)       // 77824 (img + raw), 2 CTAs/SM

template <bool RELU>
__global__ void __launch_bounds__(256, 2)
gemm_bf16_kernel(const float* __restrict__ X, int layer,
                 const float* __restrict__ bias,
                 float* __restrict__ out, uint32_t* __restrict__ out16, int nN) {
    extern __shared__ char smem[];
    char* img = smem;
    char* raw = smem + IMG_BYTES;
    const uint32_t raw_u = smem_u32(raw);

    const int tid = threadIdx.x;
    const int wid = tid >> 5;
    const int lane = tid & 31;
    const int g = lane >> 2;
    const int tg = lane & 3;
    const int warp_m = wid & 3;
    const int warp_n = wid >> 2;
    const int m0 = blockIdx.x * 128;
    const char* wbase = g_Wb + layer * 163840;

    auto stageA = [&](int kc) {
        const float* asrc = (kc < 2) ? g_agg : X;
        const int koff = (kc & 1) * 64;
        #pragma unroll
        for (int it = 0; it < 2; it++) {
            int u = tid + it * 256;
            int row = u >> 2, ks = u & 3;
            int node = m0 + row;
            const char* gp = (const char*)(asrc + (size_t)node * 128 + koff + ks * 16);
            uint32_t sp = raw_u + row * RSI + ks * 64;
            int sz = (node < nN) ? 16 : 0;
            #pragma unroll
            for (int q = 0; q < 4; q++)
                cpasync16(sp + q * 16, gp + q * 16, sz);
        }
        asm volatile("cp.async.commit_group;" ::: "memory");
    };

    auto cvtA = [&]() {
        #pragma unroll
        for (int it = 0; it < 2; it++) {
            int u = tid + it * 256;
            int row = u >> 2, ks = u & 3;
            const char* rp = raw + row * RSI + ks * 64;
            float4 f0 = *(const float4*)(rp);
            float4 f1 = *(const float4*)(rp + 16);
            float4 f2 = *(const float4*)(rp + 32);
            float4 f3 = *(const float4*)(rp + 48);
            float v[16] = {f0.x, f0.y, f0.z, f0.w, f1.x, f1.y, f1.z, f1.w,
                           f2.x, f2.y, f2.z, f2.w, f3.x, f3.y, f3.z, f3.w};
            uint32_t buf[16];
            #pragma unroll
            for (int p = 0; p < 8; p++) {
                uint32_t hi2, lo2;
                split2_bf16(v[2 * p], v[2 * p + 1], hi2, lo2);
                int pos = 2 * (p & 3) + (p >> 2);
                buf[pos * 2] = hi2;
                buf[pos * 2 + 1] = lo2;
            }
            char* dst = img + row * RSI + ks * 64;
            #pragma unroll
            for (int q = 0; q < 4; q++)
                ((uint4*)dst)[q] = make_uint4(buf[4 * q], buf[4 * q + 1],
                                              buf[4 * q + 2], buf[4 * q + 3]);
        }
    };

    float acc[2][8][4];
    #pragma unroll
    for (int t = 0; t < 2; t++)
        #pragma unroll
        for (int u = 0; u < 8; u++)
            #pragma unroll
            for (int c = 0; c < 4; c++) acc[t][u][c] = 0.f;

    stageA(0);
    asm volatile("cp.async.wait_group 0;" ::: "memory");
    cvtA();
    stageA(1);
    __syncthreads();

    #pragma unroll 1
    for (int kc = 0; kc < 4; kc++) {
        const char* wkc = wbase + kc * 40960;
        #pragma unroll
        for (int ks = 0; ks < 4; ks++) {
            uint4 qbA[4];
            #pragma unroll
            for (int uu = 0; uu < 4; uu++) {
                int n = warp_n * 64 + uu * 8 + g;
                qbA[uu] = __ldg((const uint4*)(wkc + n * 320 + ks * 64 + tg * 16));
            }
            uint32_t aH[2][4], aL[2][4];
            #pragma unroll
            for (int t = 0; t < 2; t++) {
                int r = warp_m * 32 + t * 16 + g;
                uint4 q0 = *(const uint4*)(img + r * RSI + ks * 64 + tg * 16);
                uint4 q1 = *(const uint4*)(img + (r + 8) * RSI + ks * 64 + tg * 16);
                aH[t][0] = q0.x; aH[t][1] = q1.x; aH[t][2] = q0.z; aH[t][3] = q1.z;
                aL[t][0] = q0.y; aL[t][1] = q1.y; aL[t][2] = q0.w; aL[t][3] = q1.w;
            }
            uint4 qbB[4];
            #pragma unroll
            for (int uu = 0; uu < 4; uu++) {
                int n = warp_n * 64 + (uu + 4) * 8 + g;
                qbB[uu] = __ldg((const uint4*)(wkc + n * 320 + ks * 64 + tg * 16));
            }
            #pragma unroll
            for (int uu = 0; uu < 4; uu++) {
                #pragma unroll
                for (int t = 0; t < 2; t++) {
                    MMA_BF16(acc[t][uu], aH[t][0], aH[t][1], aH[t][2], aH[t][3], qbA[uu].x, qbA[uu].z);
                    MMA_BF16(acc[t][uu], aH[t][0], aH[t][1], aH[t][2], aH[t][3], qbA[uu].y, qbA[uu].w);
                    MMA_BF16(acc[t][uu], aL[t][0], aL[t][1], aL[t][2], aL[t][3], qbA[uu].x, qbA[uu].z);
                }
            }
            #pragma unroll
            for (int uu = 0; uu < 4; uu++) {
                #pragma unroll
                for (int t = 0; t < 2; t++) {
                    MMA_BF16(acc[t][uu + 4], aH[t][0], aH[t][1], aH[t][2], aH[t][3], qbB[uu].x, qbB[uu].z);
                    MMA_BF16(acc[t][uu + 4], aH[t][0], aH[t][1], aH[t][2], aH[t][3], qbB[uu].y, qbB[uu].w);
                    MMA_BF16(acc[t][uu + 4], aL[t][0], aL[t][1], aL[t][2], aL[t][3], qbB[uu].x, qbB[uu].z);
                }
            }
        }
        if (kc < 3) {
            asm volatile("cp.async.wait_group 0;" ::: "memory");
            __syncthreads();
            cvtA();
            if (kc < 2) stageA(kc + 2);
            __syncthreads();
        }
    }

    // ---- epilogue: fp32 out + optional fp16 plane ----
    #pragma unroll
    for (int u = 0; u < 8; u++) {
        int cb = warp_n * 64 + u * 8 + 2 * tg;
        float2 bv = *(const float2*)(bias + cb);
        #pragma unroll
        for (int t = 0; t < 2; t++) {
            int r0 = m0 + warp_m * 32 + t * 16 + g;
            float2 o0 = make_float2(acc[t][u][0] + bv.x, acc[t][u][1] + bv.y);
            float2 o1 = make_float2(acc[t][u][2] + bv.x, acc[t][u][3] + bv.y);
            if (RELU) {
                o0.x = fmaxf(o0.x, 0.f); o0.y = fmaxf(o0.y, 0.f);
                o1.x = fmaxf(o1.x, 0.f); o1.y = fmaxf(o1.y, 0.f);
            }
            if (r0 < nN) {
                *(float2*)(out + (size_t)r0 * 128 + cb) = o0;
                if (out16) {
                    __half2 p = __floats2half2_rn(o0.x, o0.y);
                    out16[(size_t)r0 * 64 + (cb >> 1)] = *(uint32_t*)&p;
                }
            }
            if (r0 + 8 < nN) {
                *(float2*)(out + (size_t)(r0 + 8) * 128 + cb) = o1;
                if (out16) {
                    __half2 p = __floats2half2_rn(o1.x, o1.y);
                    out16[(size_t)(r0 + 8) * 64 + (cb >> 1)] = *(uint32_t*)&p;
                }
            }
        }
    }
}

// ---------------------------------------------------------------------------
extern "C" void kernel_launch(void* const* d_in, const int* in_sizes, int n_in,
                              void* d_out, int out_size) {
    const float* x   = (const float*)d_in[0];
    const void*  eix = d_in[1];
    const float* Wl1 = (const float*)d_in[2];
    const float* Wr1 = (const float*)d_in[3];
    const float* b1  = (const float*)d_in[4];
    const float* Wl2 = (const float*)d_in[5];
    const float* Wr2 = (const float*)d_in[6];
    const float* b2  = (const float*)d_in[7];
    float* out = (float*)d_out;

    const int nN = in_sizes[0] / D;      // 100000
    const int nE = in_sizes[1] / 2;      // 1600000

    void *degp, *hp, *x16p, *h16p;
    cudaGetSymbolAddress(&degp, g_deg);
    cudaGetSymbolAddress(&hp,   g_h);
    cudaGetSymbolAddress(&x16p, g_x16);
    cudaGetSymbolAddress(&h16p, g_h16);
    float* h = (float*)hp;

    cudaFuncSetAttribute(gemm_bf16_kernel<true>,
                         cudaFuncAttributeMaxDynamicSharedMemorySize, SM_TOTAL);
    cudaFuncSetAttribute(gemm_bf16_kernel<false>,
                         cudaFuncAttributeMaxDynamicSharedMemorySize, SM_TOTAL);

    const int edgeGrpBlocks = ((nE / 4 + 1) + 255) / 256;
    const int aggBlocks  = (int)(((long long)nN * 32 + 255) / 256);
    const int gemmBlocks = (nN + 127) / 128;
    const int scanBlocks = (nN + 1023) / 1024;    // 98
    const int n4 = nN * 32;
    const int convBlocks = (n4 + 255) / 256;

    // ---- CSR build + weight pre-split + x fp16 plane ----
    cudaMemsetAsync(degp, 0, (size_t)nN * sizeof(int));
    detect_kernel<<<1, 1>>>(eix);
    wconv_kernel<<<16, 256>>>(Wl1, Wr1, Wl2, Wr2);
    tohalf_kernel<<<convBlocks, 256>>>((const float4*)x, (uint2*)x16p, n4);
    deg_kernel<<<edgeGrpBlocks, 256>>>(eix, nE);
    blocksum_kernel<<<scanBlocks, 256>>>(nN);
    scanpart_kernel<<<1, 128>>>(scanBlocks);
    offsets_kernel<<<scanBlocks, 256>>>(nN, nE);
    fill_kernel<<<edgeGrpBlocks, 256>>>(eix, nE);

    // ---- layer 1 (gemm also emits h16 for layer-2 gather) ----
    agg16_kernel<<<aggBlocks, 256>>>((const uint2*)x16p, nN);
    gemm_bf16_kernel<true><<<gemmBlocks, 256, SM_TOTAL>>>(
        x, 0, b1, h, (uint32_t*)h16p, nN);

    // ---- layer 2 ----
    agg16_kernel<<<aggBlocks, 256>>>((const uint2*)h16p, nN);
    gemm_bf16_kernel<false><<<gemmBlocks, 256, SM_TOTAL>>>(
        h, 1, b2, out, nullptr, nN);
}

// round 12
// speedup vs baseline: 3.4233x; 1.6237x over previous
#include <cuda_runtime.h>
#include <cuda_bf16.h>
#include <cuda_fp16.h>
#include <cstdint>

#define NMAX 100000
#define D 128

typedef unsigned long long ull;

// Scratch (device globals: allocation-free per harness rules)
__device__ __align__(256) uint2 g_x16[(size_t)NMAX * 32];   // fp16 plane of x
__device__ __align__(256) uint2 g_h16[(size_t)NMAX * 32];   // fp16 plane of h (layer-1 out)
__device__ __align__(256) uint2 g_agg16[(size_t)NMAX * 32]; // fp16 plane of mean-agg
__device__ __align__(16)  char  g_W16[131072];              // fp16 weights [layer][kc][n][64]
__device__ int   g_deg[NMAX];
__device__ int   g_off[NMAX + 1];
__device__ int   g_cur[NMAX];
__device__ int   g_esrc[1600000 + 1024];                    // src sorted by dst (CSR)
__device__ float g_inv[NMAX];
__device__ int   g_part[256];
__device__ int   g_pbase[256];
__device__ int   g_idx32;

// ---------------------------------------------------------------------------
__device__ __forceinline__ uint32_t smem_u32(const void* p) {
    uint32_t a;
    asm("{ .reg .u64 t; cvta.to.shared.u64 t, %1; cvt.u32.u64 %0, t; }" : "=r"(a) : "l"(p));
    return a;
}

__device__ __forceinline__ void cpasync16(uint32_t s, const void* g, int sz) {
    asm volatile("cp.async.cg.shared.global [%0], [%1], 16, %2;"
                 :: "r"(s), "l"(g), "r"(sz) : "memory");
}

#define LDSM4(r0, r1, r2, r3, addr)                                           \
    asm volatile("ldmatrix.sync.aligned.m8n8.x4.shared.b16 {%0,%1,%2,%3},[%4];" \
                 : "=r"(r0), "=r"(r1), "=r"(r2), "=r"(r3) : "r"(addr))

#define MMA_F16(c, a0, a1, a2, a3, b0, b1)                                    \
    asm volatile("mma.sync.aligned.m16n8k16.row.col.f32.f16.f16.f32 "         \
                 "{%0,%1,%2,%3},{%4,%5,%6,%7},{%8,%9},{%0,%1,%2,%3};"         \
                 : "+f"((c)[0]), "+f"((c)[1]), "+f"((c)[2]), "+f"((c)[3])     \
                 : "r"(a0), "r"(a1), "r"(a2), "r"(a3), "r"(b0), "r"(b1))

// ---------------------------------------------------------------------------
__global__ void detect_kernel(const void* eidx) {
    const ull* p = (const ull*)eidx;
    int is32 = 0;
    #pragma unroll
    for (int i = 0; i < 4; i++)
        if (p[i] >= (1ULL << 32)) is32 = 1;
    g_idx32 = is32;
}

__device__ __forceinline__ int load_idx(const void* eidx, long long pos) {
    if (g_idx32) return ((const int*)eidx)[pos];
    return (int)(((const long long*)eidx)[pos]);
}

// fp32 -> fp16 plane conversion.
__global__ void tohalf_kernel(const float4* __restrict__ src,
                              uint2* __restrict__ dst, int n4) {
    int t = blockIdx.x * blockDim.x + threadIdx.x;
    if (t >= n4) return;
    float4 v = src[t];
    __half2 h0 = __floats2half2_rn(v.x, v.y);
    __half2 h1 = __floats2half2_rn(v.z, v.w);
    dst[t] = make_uint2(*(uint32_t*)&h0, *(uint32_t*)&h1);
}

// fp16 weight image: [layer][kc][n][64 halves], B[n][k] = W[k][n].
__global__ void wconv16_kernel(const float* __restrict__ Wl1, const float* __restrict__ Wr1,
                               const float* __restrict__ Wl2, const float* __restrict__ Wr2) {
    int unit = blockIdx.x * 256 + threadIdx.x;   // 1024 units
    if (unit >= 1024) return;
    int layer = unit >> 9;
    int kc = (unit >> 7) & 3;
    int n = unit & 127;
    const float* Wsrc = (layer == 0) ? ((kc < 2) ? Wl1 : Wr1)
                                     : ((kc < 2) ? Wl2 : Wr2);
    int kbase = (kc & 1) * 64;
    uint32_t buf[32];
    #pragma unroll
    for (int j = 0; j < 32; j++) {
        float v0 = Wsrc[(kbase + 2 * j) * 128 + n];
        float v1 = Wsrc[(kbase + 2 * j + 1) * 128 + n];
        __half2 h = __floats2half2_rn(v0, v1);
        buf[j] = *(uint32_t*)&h;
    }
    char* dst = g_W16 + (((size_t)layer * 4 + kc) * 128 + n) * 128;
    #pragma unroll
    for (int q = 0; q < 8; q++)
        ((uint4*)dst)[q] = make_uint4(buf[4 * q], buf[4 * q + 1],
                                      buf[4 * q + 2], buf[4 * q + 3]);
}

// 4 edges per thread, vectorized index loads.
__global__ void deg_kernel(const void* eidx, int nE) {
    int t = blockIdx.x * blockDim.x + threadIdx.x;
    int ngrp = nE >> 2;
    if (t < ngrp) {
        int d0, d1, d2, d3;
        if (g_idx32) {
            int4 v = ((const int4*)eidx)[ngrp + t];
            d0 = v.x; d1 = v.y; d2 = v.z; d3 = v.w;
        } else {
            longlong2 v0 = ((const longlong2*)eidx)[(nE >> 1) + t * 2];
            longlong2 v1 = ((const longlong2*)eidx)[(nE >> 1) + t * 2 + 1];
            d0 = (int)v0.x; d1 = (int)v0.y; d2 = (int)v1.x; d3 = (int)v1.y;
        }
        atomicAdd(&g_deg[d0], 1);
        atomicAdd(&g_deg[d1], 1);
        atomicAdd(&g_deg[d2], 1);
        atomicAdd(&g_deg[d3], 1);
    } else if (t == ngrp) {
        for (int e = ngrp * 4; e < nE; e++)
            atomicAdd(&g_deg[load_idx(eidx, (long long)nE + e)], 1);
    }
}

// Parallel 3-phase exclusive scan over degrees.
__global__ void blocksum_kernel(int nN) {
    __shared__ int ws[8];
    int t = threadIdx.x;
    int base = blockIdx.x * 1024 + t * 4;
    int s = 0;
    #pragma unroll
    for (int j = 0; j < 4; j++) {
        int i = base + j;
        if (i < nN) s += g_deg[i];
    }
    #pragma unroll
    for (int o = 16; o > 0; o >>= 1) s += __shfl_down_sync(~0u, s, o);
    if ((t & 31) == 0) ws[t >> 5] = s;
    __syncthreads();
    if (t < 8) {
        int v = ws[t];
        #pragma unroll
        for (int o = 4; o > 0; o >>= 1) v += __shfl_down_sync(0xff, v, o);
        if (t == 0) g_part[blockIdx.x] = v;
    }
}

__global__ void scanpart_kernel(int nb) {
    __shared__ int sm[128];
    int t = threadIdx.x;
    int v = (t < nb) ? g_part[t] : 0;
    sm[t] = v;
    __syncthreads();
    for (int o = 1; o < 128; o <<= 1) {
        int u = (t >= o) ? sm[t - o] : 0;
        __syncthreads();
        sm[t] += u;
        __syncthreads();
    }
    g_pbase[t] = (t == 0) ? 0 : sm[t - 1];
}

__global__ void offsets_kernel(int nN, int nE) {
    __shared__ int warp_tot[8];
    int t = threadIdx.x;
    int blk = blockIdx.x;
    int lane = t & 31, w = t >> 5;
    int base = blk * 1024 + t * 4;
    int d[4];
    int s = 0;
    #pragma unroll
    for (int j = 0; j < 4; j++) {
        int i = base + j;
        d[j] = (i < nN) ? g_deg[i] : 0;
        s += d[j];
    }
    int inc = s;
    #pragma unroll
    for (int o = 1; o < 32; o <<= 1) {
        int u = __shfl_up_sync(~0u, inc, o);
        if (lane >= o) inc += u;
    }
    if (lane == 31) warp_tot[w] = inc;
    __syncthreads();
    if (t < 8) {
        int v = warp_tot[t];
        #pragma unroll
        for (int o = 1; o < 8; o <<= 1) {
            int u = __shfl_up_sync(0xff, v, o);
            if (t >= o) v += u;
        }
        warp_tot[t] = v;
    }
    __syncthreads();
    int run = g_pbase[blk] + (inc - s) + ((w > 0) ? warp_tot[w - 1] : 0);
    #pragma unroll
    for (int j = 0; j < 4; j++) {
        int i = base + j;
        if (i < nN) {
            g_off[i] = run;
            g_cur[i] = run;
            g_inv[i] = 1.0f / (float)(d[j] > 0 ? d[j] : 1);
            run += d[j];
        }
    }
    if (blk == 0 && t == 0) g_off[nN] = nE;
}

__global__ void fill_kernel(const void* eidx, int nE) {
    int t = blockIdx.x * blockDim.x + threadIdx.x;
    int ngrp = nE >> 2;
    if (t < ngrp) {
        int s0, s1, s2, s3, d0, d1, d2, d3;
        if (g_idx32) {
            int4 sv = ((const int4*)eidx)[t];
            int4 dv = ((const int4*)eidx)[ngrp + t];
            s0 = sv.x; s1 = sv.y; s2 = sv.z; s3 = sv.w;
            d0 = dv.x; d1 = dv.y; d2 = dv.z; d3 = dv.w;
        } else {
            longlong2 a0 = ((const longlong2*)eidx)[t * 2];
            longlong2 a1 = ((const longlong2*)eidx)[t * 2 + 1];
            longlong2 b0 = ((const longlong2*)eidx)[(nE >> 1) + t * 2];
            longlong2 b1 = ((const longlong2*)eidx)[(nE >> 1) + t * 2 + 1];
            s0 = (int)a0.x; s1 = (int)a0.y; s2 = (int)a1.x; s3 = (int)a1.y;
            d0 = (int)b0.x; d1 = (int)b0.y; d2 = (int)b1.x; d3 = (int)b1.y;
        }
        g_esrc[atomicAdd(&g_cur[d0], 1)] = s0;
        g_esrc[atomicAdd(&g_cur[d1], 1)] = s1;
        g_esrc[atomicAdd(&g_cur[d2], 1)] = s2;
        g_esrc[atomicAdd(&g_cur[d3], 1)] = s3;
    } else if (t == ngrp) {
        for (int e = ngrp * 4; e < nE; e++) {
            int src = load_idx(eidx, e);
            int dst = load_idx(eidx, (long long)nE + e);
            g_esrc[atomicAdd(&g_cur[dst], 1)] = src;
        }
    }
}

// ---------------------------------------------------------------------------
// fp16-plane gather aggregation; fp32 accum; writes fp16 mean plane.
__device__ __forceinline__ void acc4h(float4& a, uint2 v) {
    float2 p = __half22float2(*(__half2*)&v.x);
    float2 q = __half22float2(*(__half2*)&v.y);
    a.x += p.x; a.y += p.y; a.z += q.x; a.w += q.y;
}

__global__ void agg16_kernel(const uint2* __restrict__ f16, int nN) {
    int gtid = blockIdx.x * blockDim.x + threadIdx.x;
    int w = gtid >> 5;
    int lane = gtid & 31;
    if (w >= nN) return;
    int beg = g_off[w], end = g_off[w + 1];
    float4 a0 = make_float4(0.f, 0.f, 0.f, 0.f);
    float4 a1 = a0;
    int i = beg;
    for (; i + 3 < end; i += 4) {
        int s0 = g_esrc[i], s1 = g_esrc[i + 1];
        int s2 = g_esrc[i + 2], s3 = g_esrc[i + 3];
        uint2 v0 = f16[(size_t)s0 * 32 + lane];
        uint2 v1 = f16[(size_t)s1 * 32 + lane];
        uint2 v2 = f16[(size_t)s2 * 32 + lane];
        uint2 v3 = f16[(size_t)s3 * 32 + lane];
        acc4h(a0, v0); acc4h(a1, v1); acc4h(a0, v2); acc4h(a1, v3);
    }
    for (; i < end; i++) {
        uint2 v0 = f16[(size_t)g_esrc[i] * 32 + lane];
        acc4h(a0, v0);
    }
    float inv = g_inv[w];
    __half2 o0 = __floats2half2_rn((a0.x + a1.x) * inv, (a0.y + a1.y) * inv);
    __half2 o1 = __floats2half2_rn((a0.z + a1.z) * inv, (a0.w + a1.w) * inv);
    g_agg16[(size_t)w * 32 + lane] = make_uint2(*(uint32_t*)&o0, *(uint32_t*)&o1);
}

// ---------------------------------------------------------------------------
// fp16 mma.sync GEMM:
//   out[128-tile,128] = concat(mean16,x16)[128,256] @ W16[256,128] + b
// Block 256 thr (8 warps), warp tile 32x64. K in 4 chunks of 64.
// SMEM rows padded to 144B -> ldmatrix 8-row accesses rotate 4 banks/row,
// covering all 32 banks exactly once (conflict-free).
#define RS16 144
#define TILE16 (128 * RS16)            // 18432
#define SM_TOTAL (2 * TILE16)          // 36864, 2 CTAs/SM

template <bool RELU, bool EMIT16>
__global__ void __launch_bounds__(256, 2)
gemm_f16_kernel(const uint2* __restrict__ xs16, int layer,
                const float* __restrict__ bias,
                float* __restrict__ out, uint32_t* __restrict__ out16, int nN) {
    extern __shared__ char smem[];
    const uint32_t sA_u = smem_u32(smem);
    const uint32_t sB_u = sA_u + TILE16;

    const int tid = threadIdx.x;
    const int wid = tid >> 5;
    const int lane = tid & 31;
    const int g = lane >> 2;
    const int tg = lane & 3;
    const int warp_m = wid & 3;     // rows warp_m*32..+31
    const int warp_n = wid >> 2;    // cols warp_n*64..+63
    const int m0 = blockIdx.x * 128;

    // per-lane ldmatrix base offsets (sel = lane>>3)
    // A: row += (sel&1)*8, col += (sel>>1)*16
    uint32_t offA[2];
    #pragma unroll
    for (int t = 0; t < 2; t++)
        offA[t] = sA_u + (uint32_t)((warp_m * 32 + t * 16 + (lane & 7)
                   + ((lane >> 3) & 1) * 8) * RS16 + ((lane >> 4) & 1) * 16);
    // B: row += (sel>>1)*8, col += (sel&1)*16   (covers 2 n-tiles per ldmatrix.x4)
    uint32_t offB[4];
    #pragma unroll
    for (int up = 0; up < 4; up++)
        offB[up] = sB_u + (uint32_t)((warp_n * 64 + up * 16 + (lane & 7)
                   + ((lane >> 4) & 1) * 8) * RS16 + ((lane >> 3) & 1) * 16);

    auto stage = [&](int kc) {
        const char* a16 = (const char*)((kc < 2) ? g_agg16 : xs16);
        const int koffB = (kc & 1) * 128;   // byte offset within 256B fp16 row
        #pragma unroll
        for (int it = 0; it < 4; it++) {
            int i = tid + it * 256;          // 0..1023
            int row = i >> 3, q = i & 7;
            int node = m0 + row;
            const char* gp = a16 + (size_t)node * 256 + koffB + q * 16;
            cpasync16(sA_u + row * RS16 + q * 16, gp, (node < nN) ? 16 : 0);
        }
        const char* wsrc = g_W16 + ((size_t)layer * 4 + kc) * 16384;
        #pragma unroll
        for (int it = 0; it < 4; it++) {
            int i = tid + it * 256;
            int n = i >> 3, q = i & 7;
            cpasync16(sB_u + n * RS16 + q * 16, wsrc + n * 128 + q * 16, 16);
        }
        asm volatile("cp.async.commit_group;" ::: "memory");
    };

    float acc[2][8][4];
    #pragma unroll
    for (int t = 0; t < 2; t++)
        #pragma unroll
        for (int u = 0; u < 8; u++)
            #pragma unroll
            for (int c = 0; c < 4; c++) acc[t][u][c] = 0.f;

    #pragma unroll 1
    for (int kc = 0; kc < 4; kc++) {
        stage(kc);
        asm volatile("cp.async.wait_group 0;" ::: "memory");
        __syncthreads();
        #pragma unroll
        for (int ks = 0; ks < 4; ks++) {
            uint32_t a[2][4];
            LDSM4(a[0][0], a[0][1], a[0][2], a[0][3], offA[0] + ks * 32);
            LDSM4(a[1][0], a[1][1], a[1][2], a[1][3], offA[1] + ks * 32);
            uint32_t b[8][2];
            #pragma unroll
            for (int up = 0; up < 4; up++)
                LDSM4(b[2 * up][0], b[2 * up][1], b[2 * up + 1][0], b[2 * up + 1][1],
                      offB[up] + ks * 32);
            #pragma unroll
            for (int u = 0; u < 8; u++)
                #pragma unroll
                for (int t = 0; t < 2; t++)
                    MMA_F16(acc[t][u], a[t][0], a[t][1], a[t][2], a[t][3],
                            b[u][0], b[u][1]);
        }
        __syncthreads();   // buffer reuse
    }

    // ---- epilogue ----
    #pragma unroll
    for (int u = 0; u < 8; u++) {
        int cb = warp_n * 64 + u * 8 + 2 * tg;
        float2 bv = *(const float2*)(bias + cb);
        #pragma unroll
        for (int t = 0; t < 2; t++) {
            int r0 = m0 + warp_m * 32 + t * 16 + g;
            float2 o0 = make_float2(acc[t][u][0] + bv.x, acc[t][u][1] + bv.y);
            float2 o1 = make_float2(acc[t][u][2] + bv.x, acc[t][u][3] + bv.y);
            if (RELU) {
                o0.x = fmaxf(o0.x, 0.f); o0.y = fmaxf(o0.y, 0.f);
                o1.x = fmaxf(o1.x, 0.f); o1.y = fmaxf(o1.y, 0.f);
            }
            if (EMIT16) {
                if (r0 < nN) {
                    __half2 p = __floats2half2_rn(o0.x, o0.y);
                    out16[(size_t)r0 * 64 + (cb >> 1)] = *(uint32_t*)&p;
                }
                if (r0 + 8 < nN) {
                    __half2 p = __floats2half2_rn(o1.x, o1.y);
                    out16[(size_t)(r0 + 8) * 64 + (cb >> 1)] = *(uint32_t*)&p;
                }
            } else {
                if (r0 < nN)     *(float2*)(out + (size_t)r0 * 128 + cb) = o0;
                if (r0 + 8 < nN) *(float2*)(out + (size_t)(r0 + 8) * 128 + cb) = o1;
            }
        }
    }
}

// ---------------------------------------------------------------------------
extern "C" void kernel_launch(void* const* d_in, const int* in_sizes, int n_in,
                              void* d_out, int out_size) {
    const float* x   = (const float*)d_in[0];
    const void*  eix = d_in[1];
    const float* Wl1 = (const float*)d_in[2];
    const float* Wr1 = (const float*)d_in[3];
    const float* b1  = (const float*)d_in[4];
    const float* Wl2 = (const float*)d_in[5];
    const float* Wr2 = (const float*)d_in[6];
    const float* b2  = (const float*)d_in[7];
    float* out = (float*)d_out;

    const int nN = in_sizes[0] / D;      // 100000
    const int nE = in_sizes[1] / 2;      // 1600000

    void *degp, *x16p, *h16p;
    cudaGetSymbolAddress(&degp, g_deg);
    cudaGetSymbolAddress(&x16p, g_x16);
    cudaGetSymbolAddress(&h16p, g_h16);

    cudaFuncSetAttribute(gemm_f16_kernel<true, true>,
                         cudaFuncAttributeMaxDynamicSharedMemorySize, SM_TOTAL);
    cudaFuncSetAttribute(gemm_f16_kernel<false, false>,
                         cudaFuncAttributeMaxDynamicSharedMemorySize, SM_TOTAL);

    const int edgeGrpBlocks = ((nE / 4 + 1) + 255) / 256;
    const int aggBlocks  = (int)(((long long)nN * 32 + 255) / 256);
    const int gemmBlocks = (nN + 127) / 128;
    const int scanBlocks = (nN + 1023) / 1024;    // 98
    const int n4 = nN * 32;
    const int convBlocks = (n4 + 255) / 256;

    // ---- CSR build + weight/x fp16 conversion ----
    cudaMemsetAsync(degp, 0, (size_t)nN * sizeof(int));
    detect_kernel<<<1, 1>>>(eix);
    wconv16_kernel<<<4, 256>>>(Wl1, Wr1, Wl2, Wr2);
    tohalf_kernel<<<convBlocks, 256>>>((const float4*)x, (uint2*)x16p, n4);
    deg_kernel<<<edgeGrpBlocks, 256>>>(eix, nE);
    blocksum_kernel<<<scanBlocks, 256>>>(nN);
    scanpart_kernel<<<1, 128>>>(scanBlocks);
    offsets_kernel<<<scanBlocks, 256>>>(nN, nE);
    fill_kernel<<<edgeGrpBlocks, 256>>>(eix, nE);

    // ---- layer 1: emits only the fp16 plane h16 ----
    agg16_kernel<<<aggBlocks, 256>>>((const uint2*)x16p, nN);
    gemm_f16_kernel<true, true><<<gemmBlocks, 256, SM_TOTAL>>>(
        (const uint2*)x16p, 0, b1, nullptr, (uint32_t*)h16p, nN);

    // ---- layer 2: fp32 output ----
    agg16_kernel<<<aggBlocks, 256>>>((const uint2*)h16p, nN);
    gemm_f16_kernel<false, false><<<gemmBlocks, 256, SM_TOTAL>>>(
        (const uint2*)h16p, 1, b2, out, nullptr, nN);
}

// round 13
// speedup vs baseline: 3.5407x; 1.0343x over previous
#include <cuda_runtime.h>
#include <cuda_bf16.h>
#include <cuda_fp16.h>
#include <cstdint>

#define NMAX 100000
#define D 128

typedef unsigned long long ull;

// Scratch (device globals: allocation-free per harness rules)
__device__ __align__(256) uint2 g_x16[(size_t)NMAX * 32];   // fp16 plane of x
__device__ __align__(256) uint2 g_h16[(size_t)NMAX * 32];   // fp16 plane of h (layer-1 out)
__device__ __align__(256) uint2 g_agg16[(size_t)NMAX * 32]; // fp16 plane of mean-agg
__device__ __align__(16)  char  g_W16[131072];              // fp16 weights [layer][kc][n][64]
__device__ int   g_deg[NMAX];
__device__ int   g_off[NMAX + 1];
__device__ int   g_cur[NMAX];
__device__ int   g_esrc[1600000 + 1024];                    // src sorted by dst (CSR)
__device__ float g_inv[NMAX];
__device__ int   g_part[256];
__device__ int   g_pbase[256];
__device__ int   g_idx32;

// ---------------------------------------------------------------------------
__device__ __forceinline__ uint32_t smem_u32(const void* p) {
    uint32_t a;
    asm("{ .reg .u64 t; cvta.to.shared.u64 t, %1; cvt.u32.u64 %0, t; }" : "=r"(a) : "l"(p));
    return a;
}

__device__ __forceinline__ void cpasync16(uint32_t s, const void* g, int sz) {
    asm volatile("cp.async.cg.shared.global [%0], [%1], 16, %2;"
                 :: "r"(s), "l"(g), "r"(sz) : "memory");
}

#define LDSM4(r0, r1, r2, r3, addr)                                           \
    asm volatile("ldmatrix.sync.aligned.m8n8.x4.shared.b16 {%0,%1,%2,%3},[%4];" \
                 : "=r"(r0), "=r"(r1), "=r"(r2), "=r"(r3) : "r"(addr))

#define MMA_F16(c, a0, a1, a2, a3, b0, b1)                                    \
    asm volatile("mma.sync.aligned.m16n8k16.row.col.f32.f16.f16.f32 "         \
                 "{%0,%1,%2,%3},{%4,%5,%6,%7},{%8,%9},{%0,%1,%2,%3};"         \
                 : "+f"((c)[0]), "+f"((c)[1]), "+f"((c)[2]), "+f"((c)[3])     \
                 : "r"(a0), "r"(a1), "r"(a2), "r"(a3), "r"(b0), "r"(b1))

// ---------------------------------------------------------------------------
__global__ void detect_kernel(const void* eidx) {
    const ull* p = (const ull*)eidx;
    int is32 = 0;
    #pragma unroll
    for (int i = 0; i < 4; i++)
        if (p[i] >= (1ULL << 32)) is32 = 1;
    g_idx32 = is32;
}

__device__ __forceinline__ int load_idx(const void* eidx, long long pos) {
    if (g_idx32) return ((const int*)eidx)[pos];
    return (int)(((const long long*)eidx)[pos]);
}

// fp32 -> fp16 plane conversion.
__global__ void tohalf_kernel(const float4* __restrict__ src,
                              uint2* __restrict__ dst, int n4) {
    int t = blockIdx.x * blockDim.x + threadIdx.x;
    if (t >= n4) return;
    float4 v = src[t];
    __half2 h0 = __floats2half2_rn(v.x, v.y);
    __half2 h1 = __floats2half2_rn(v.z, v.w);
    dst[t] = make_uint2(*(uint32_t*)&h0, *(uint32_t*)&h1);
}

// fp16 weight image: [layer][kc][n][64 halves], B[n][k] = W[k][n].
__global__ void wconv16_kernel(const float* __restrict__ Wl1, const float* __restrict__ Wr1,
                               const float* __restrict__ Wl2, const float* __restrict__ Wr2) {
    int unit = blockIdx.x * 256 + threadIdx.x;   // 1024 units
    if (unit >= 1024) return;
    int layer = unit >> 9;
    int kc = (unit >> 7) & 3;
    int n = unit & 127;
    const float* Wsrc = (layer == 0) ? ((kc < 2) ? Wl1 : Wr1)
                                     : ((kc < 2) ? Wl2 : Wr2);
    int kbase = (kc & 1) * 64;
    uint32_t buf[32];
    #pragma unroll
    for (int j = 0; j < 32; j++) {
        float v0 = Wsrc[(kbase + 2 * j) * 128 + n];
        float v1 = Wsrc[(kbase + 2 * j + 1) * 128 + n];
        __half2 h = __floats2half2_rn(v0, v1);
        buf[j] = *(uint32_t*)&h;
    }
    char* dst = g_W16 + (((size_t)layer * 4 + kc) * 128 + n) * 128;
    #pragma unroll
    for (int q = 0; q < 8; q++)
        ((uint4*)dst)[q] = make_uint4(buf[4 * q], buf[4 * q + 1],
                                      buf[4 * q + 2], buf[4 * q + 3]);
}

// 4 edges per thread, vectorized index loads.
__global__ void deg_kernel(const void* eidx, int nE) {
    int t = blockIdx.x * blockDim.x + threadIdx.x;
    int ngrp = nE >> 2;
    if (t < ngrp) {
        int d0, d1, d2, d3;
        if (g_idx32) {
            int4 v = ((const int4*)eidx)[ngrp + t];
            d0 = v.x; d1 = v.y; d2 = v.z; d3 = v.w;
        } else {
            longlong2 v0 = ((const longlong2*)eidx)[(nE >> 1) + t * 2];
            longlong2 v1 = ((const longlong2*)eidx)[(nE >> 1) + t * 2 + 1];
            d0 = (int)v0.x; d1 = (int)v0.y; d2 = (int)v1.x; d3 = (int)v1.y;
        }
        atomicAdd(&g_deg[d0], 1);
        atomicAdd(&g_deg[d1], 1);
        atomicAdd(&g_deg[d2], 1);
        atomicAdd(&g_deg[d3], 1);
    } else if (t == ngrp) {
        for (int e = ngrp * 4; e < nE; e++)
            atomicAdd(&g_deg[load_idx(eidx, (long long)nE + e)], 1);
    }
}

// Parallel 3-phase exclusive scan over degrees.
__global__ void blocksum_kernel(int nN) {
    __shared__ int ws[8];
    int t = threadIdx.x;
    int base = blockIdx.x * 1024 + t * 4;
    int s = 0;
    #pragma unroll
    for (int j = 0; j < 4; j++) {
        int i = base + j;
        if (i < nN) s += g_deg[i];
    }
    #pragma unroll
    for (int o = 16; o > 0; o >>= 1) s += __shfl_down_sync(~0u, s, o);
    if ((t & 31) == 0) ws[t >> 5] = s;
    __syncthreads();
    if (t < 8) {
        int v = ws[t];
        #pragma unroll
        for (int o = 4; o > 0; o >>= 1) v += __shfl_down_sync(0xff, v, o);
        if (t == 0) g_part[blockIdx.x] = v;
    }
}

__global__ void scanpart_kernel(int nb) {
    __shared__ int sm[128];
    int t = threadIdx.x;
    int v = (t < nb) ? g_part[t] : 0;
    sm[t] = v;
    __syncthreads();
    for (int o = 1; o < 128; o <<= 1) {
        int u = (t >= o) ? sm[t - o] : 0;
        __syncthreads();
        sm[t] += u;
        __syncthreads();
    }
    g_pbase[t] = (t == 0) ? 0 : sm[t - 1];
}

__global__ void offsets_kernel(int nN, int nE) {
    __shared__ int warp_tot[8];
    int t = threadIdx.x;
    int blk = blockIdx.x;
    int lane = t & 31, w = t >> 5;
    int base = blk * 1024 + t * 4;
    int d[4];
    int s = 0;
    #pragma unroll
    for (int j = 0; j < 4; j++) {
        int i = base + j;
        d[j] = (i < nN) ? g_deg[i] : 0;
        s += d[j];
    }
    int inc = s;
    #pragma unroll
    for (int o = 1; o < 32; o <<= 1) {
        int u = __shfl_up_sync(~0u, inc, o);
        if (lane >= o) inc += u;
    }
    if (lane == 31) warp_tot[w] = inc;
    __syncthreads();
    if (t < 8) {
        int v = warp_tot[t];
        #pragma unroll
        for (int o = 1; o < 8; o <<= 1) {
            int u = __shfl_up_sync(0xff, v, o);
            if (t >= o) v += u;
        }
        warp_tot[t] = v;
    }
    __syncthreads();
    int run = g_pbase[blk] + (inc - s) + ((w > 0) ? warp_tot[w - 1] : 0);
    #pragma unroll
    for (int j = 0; j < 4; j++) {
        int i = base + j;
        if (i < nN) {
            g_off[i] = run;
            g_cur[i] = run;
            g_inv[i] = 1.0f / (float)(d[j] > 0 ? d[j] : 1);
            run += d[j];
        }
    }
    if (blk == 0 && t == 0) g_off[nN] = nE;
}

__global__ void fill_kernel(const void* eidx, int nE) {
    int t = blockIdx.x * blockDim.x + threadIdx.x;
    int ngrp = nE >> 2;
    if (t < ngrp) {
        int s0, s1, s2, s3, d0, d1, d2, d3;
        if (g_idx32) {
            int4 sv = ((const int4*)eidx)[t];
            int4 dv = ((const int4*)eidx)[ngrp + t];
            s0 = sv.x; s1 = sv.y; s2 = sv.z; s3 = sv.w;
            d0 = dv.x; d1 = dv.y; d2 = dv.z; d3 = dv.w;
        } else {
            longlong2 a0 = ((const longlong2*)eidx)[t * 2];
            longlong2 a1 = ((const longlong2*)eidx)[t * 2 + 1];
            longlong2 b0 = ((const longlong2*)eidx)[(nE >> 1) + t * 2];
            longlong2 b1 = ((const longlong2*)eidx)[(nE >> 1) + t * 2 + 1];
            s0 = (int)a0.x; s1 = (int)a0.y; s2 = (int)a1.x; s3 = (int)a1.y;
            d0 = (int)b0.x; d1 = (int)b0.y; d2 = (int)b1.x; d3 = (int)b1.y;
        }
        g_esrc[atomicAdd(&g_cur[d0], 1)] = s0;
        g_esrc[atomicAdd(&g_cur[d1], 1)] = s1;
        g_esrc[atomicAdd(&g_cur[d2], 1)] = s2;
        g_esrc[atomicAdd(&g_cur[d3], 1)] = s3;
    } else if (t == ngrp) {
        for (int e = ngrp * 4; e < nE; e++) {
            int src = load_idx(eidx, e);
            int dst = load_idx(eidx, (long long)nE + e);
            g_esrc[atomicAdd(&g_cur[dst], 1)] = src;
        }
    }
}

// ---------------------------------------------------------------------------
// fp16-plane gather aggregation; fp32 accum; writes fp16 mean plane.
__device__ __forceinline__ void acc4h(float4& a, uint2 v) {
    float2 p = __half22float2(*(__half2*)&v.x);
    float2 q = __half22float2(*(__half2*)&v.y);
    a.x += p.x; a.y += p.y; a.z += q.x; a.w += q.y;
}

__global__ void agg16_kernel(const uint2* __restrict__ f16, int nN) {
    int gtid = blockIdx.x * blockDim.x + threadIdx.x;
    int w = gtid >> 5;
    int lane = gtid & 31;
    if (w >= nN) return;
    int beg = g_off[w], end = g_off[w + 1];
    float4 a0 = make_float4(0.f, 0.f, 0.f, 0.f);
    float4 a1 = a0;
    int i = beg;
    for (; i + 3 < end; i += 4) {
        int s0 = g_esrc[i], s1 = g_esrc[i + 1];
        int s2 = g_esrc[i + 2], s3 = g_esrc[i + 3];
        uint2 v0 = f16[(size_t)s0 * 32 + lane];
        uint2 v1 = f16[(size_t)s1 * 32 + lane];
        uint2 v2 = f16[(size_t)s2 * 32 + lane];
        uint2 v3 = f16[(size_t)s3 * 32 + lane];
        acc4h(a0, v0); acc4h(a1, v1); acc4h(a0, v2); acc4h(a1, v3);
    }
    for (; i < end; i++) {
        uint2 v0 = f16[(size_t)g_esrc[i] * 32 + lane];
        acc4h(a0, v0);
    }
    float inv = g_inv[w];
    __half2 o0 = __floats2half2_rn((a0.x + a1.x) * inv, (a0.y + a1.y) * inv);
    __half2 o1 = __floats2half2_rn((a0.z + a1.z) * inv, (a0.w + a1.w) * inv);
    g_agg16[(size_t)w * 32 + lane] = make_uint2(*(uint32_t*)&o0, *(uint32_t*)&o1);
}

// ---------------------------------------------------------------------------
// fp16 mma.sync GEMM, double-buffered:
//   out[128-tile,128] = concat(mean16,x16)[128,256] @ W16[256,128] + b
// Block 256 thr (8 warps), warp tile 32x64. K in 4 chunks of 64; chunk kc+1's
// cp.async streams during mma(kc) (wait_group 1).
#define RS16 144
#define TILE16 (128 * RS16)            // 18432
#define BUF16 (2 * TILE16)             // A+B one stage
#define SM_TOTAL (2 * BUF16)           // 73728, 2 CTAs/SM

template <bool RELU, bool EMIT16>
__global__ void __launch_bounds__(256, 2)
gemm_f16_kernel(const uint2* __restrict__ xs16, int layer,
                const float* __restrict__ bias,
                float* __restrict__ out, uint32_t* __restrict__ out16, int nN) {
    extern __shared__ char smem[];
    const uint32_t s0_u = smem_u32(smem);

    const int tid = threadIdx.x;
    const int wid = tid >> 5;
    const int lane = tid & 31;
    const int g = lane >> 2;
    const int tg = lane & 3;
    const int warp_m = wid & 3;     // rows warp_m*32..+31
    const int warp_n = wid >> 2;    // cols warp_n*64..+63
    const int m0 = blockIdx.x * 128;

    // per-lane ldmatrix base offsets within a buffer (sel = lane>>3)
    uint32_t offA[2];
    #pragma unroll
    for (int t = 0; t < 2; t++)
        offA[t] = (uint32_t)((warp_m * 32 + t * 16 + (lane & 7)
                   + ((lane >> 3) & 1) * 8) * RS16 + ((lane >> 4) & 1) * 16);
    uint32_t offB[4];
    #pragma unroll
    for (int up = 0; up < 4; up++)
        offB[up] = (uint32_t)(TILE16 + (warp_n * 64 + up * 16 + (lane & 7)
                   + ((lane >> 4) & 1) * 8) * RS16 + ((lane >> 3) & 1) * 16);

    auto stage = [&](int kc) {
        const uint32_t base = s0_u + (kc & 1) * BUF16;
        const char* a16 = (const char*)((kc < 2) ? g_agg16 : xs16);
        const int koffB = (kc & 1) * 128;   // byte offset within 256B fp16 row
        #pragma unroll
        for (int it = 0; it < 4; it++) {
            int i = tid + it * 256;          // 0..1023
            int row = i >> 3, q = i & 7;
            int node = m0 + row;
            const char* gp = a16 + (size_t)node * 256 + koffB + q * 16;
            cpasync16(base + row * RS16 + q * 16, gp, (node < nN) ? 16 : 0);
        }
        const char* wsrc = g_W16 + ((size_t)layer * 4 + kc) * 16384;
        #pragma unroll
        for (int it = 0; it < 4; it++) {
            int i = tid + it * 256;
            int n = i >> 3, q = i & 7;
            cpasync16(base + TILE16 + n * RS16 + q * 16, wsrc + n * 128 + q * 16, 16);
        }
        asm volatile("cp.async.commit_group;" ::: "memory");
    };

    float acc[2][8][4];
    #pragma unroll
    for (int t = 0; t < 2; t++)
        #pragma unroll
        for (int u = 0; u < 8; u++)
            #pragma unroll
            for (int c = 0; c < 4; c++) acc[t][u][c] = 0.f;

    stage(0);
    #pragma unroll 1
    for (int kc = 0; kc < 4; kc++) {
        if (kc < 3) stage(kc + 1);   // buffer (kc+1)&1: last read at mma(kc-1), fenced below
        if (kc < 3)
            asm volatile("cp.async.wait_group 1;" ::: "memory");
        else
            asm volatile("cp.async.wait_group 0;" ::: "memory");
        __syncthreads();             // stage(kc) visible to all warps
        const uint32_t base = s0_u + (kc & 1) * BUF16;
        #pragma unroll
        for (int ks = 0; ks < 4; ks++) {
            uint32_t a[2][4];
            LDSM4(a[0][0], a[0][1], a[0][2], a[0][3], base + offA[0] + ks * 32);
            LDSM4(a[1][0], a[1][1], a[1][2], a[1][3], base + offA[1] + ks * 32);
            uint32_t b[8][2];
            #pragma unroll
            for (int up = 0; up < 4; up++)
                LDSM4(b[2 * up][0], b[2 * up][1], b[2 * up + 1][0], b[2 * up + 1][1],
                      base + offB[up] + ks * 32);
            #pragma unroll
            for (int u = 0; u < 8; u++)
                #pragma unroll
                for (int t = 0; t < 2; t++)
                    MMA_F16(acc[t][u], a[t][0], a[t][1], a[t][2], a[t][3],
                            b[u][0], b[u][1]);
        }
        __syncthreads();             // all warps done with buffer kc&1
    }

    // ---- epilogue ----
    #pragma unroll
    for (int u = 0; u < 8; u++) {
        int cb = warp_n * 64 + u * 8 + 2 * tg;
        float2 bv = *(const float2*)(bias + cb);
        #pragma unroll
        for (int t = 0; t < 2; t++) {
            int r0 = m0 + warp_m * 32 + t * 16 + g;
            float2 o0 = make_float2(acc[t][u][0] + bv.x, acc[t][u][1] + bv.y);
            float2 o1 = make_float2(acc[t][u][2] + bv.x, acc[t][u][3] + bv.y);
            if (RELU) {
                o0.x = fmaxf(o0.x, 0.f); o0.y = fmaxf(o0.y, 0.f);
                o1.x = fmaxf(o1.x, 0.f); o1.y = fmaxf(o1.y, 0.f);
            }
            if (EMIT16) {
                if (r0 < nN) {
                    __half2 p = __floats2half2_rn(o0.x, o0.y);
                    out16[(size_t)r0 * 64 + (cb >> 1)] = *(uint32_t*)&p;
                }
                if (r0 + 8 < nN) {
                    __half2 p = __floats2half2_rn(o1.x, o1.y);
                    out16[(size_t)(r0 + 8) * 64 + (cb >> 1)] = *(uint32_t*)&p;
                }
            } else {
                if (r0 < nN)     *(float2*)(out + (size_t)r0 * 128 + cb) = o0;
                if (r0 + 8 < nN) *(float2*)(out + (size_t)(r0 + 8) * 128 + cb) = o1;
            }
        }
    }
}

// ---------------------------------------------------------------------------
extern "C" void kernel_launch(void* const* d_in, const int* in_sizes, int n_in,
                              void* d_out, int out_size) {
    const float* x   = (const float*)d_in[0];
    const void*  eix = d_in[1];
    const float* Wl1 = (const float*)d_in[2];
    const float* Wr1 = (const float*)d_in[3];
    const float* b1  = (const float*)d_in[4];
    const float* Wl2 = (const float*)d_in[5];
    const float* Wr2 = (const float*)d_in[6];
    const float* b2  = (const float*)d_in[7];
    float* out = (float*)d_out;

    const int nN = in_sizes[0] / D;      // 100000
    const int nE = in_sizes[1] / 2;      // 1600000

    void *degp, *x16p, *h16p;
    cudaGetSymbolAddress(&degp, g_deg);
    cudaGetSymbolAddress(&x16p, g_x16);
    cudaGetSymbolAddress(&h16p, g_h16);

    cudaFuncSetAttribute(gemm_f16_kernel<true, true>,
                         cudaFuncAttributeMaxDynamicSharedMemorySize, SM_TOTAL);
    cudaFuncSetAttribute(gemm_f16_kernel<false, false>,
                         cudaFuncAttributeMaxDynamicSharedMemorySize, SM_TOTAL);

    const int edgeGrpBlocks = ((nE / 4 + 1) + 255) / 256;
    const int aggBlocks  = (int)(((long long)nN * 32 + 255) / 256);
    const int gemmBlocks = (nN + 127) / 128;
    const int scanBlocks = (nN + 1023) / 1024;    // 98
    const int n4 = nN * 32;
    const int convBlocks = (n4 + 255) / 256;

    // ---- CSR build + weight/x fp16 conversion ----
    cudaMemsetAsync(degp, 0, (size_t)nN * sizeof(int));
    detect_kernel<<<1, 1>>>(eix);
    wconv16_kernel<<<4, 256>>>(Wl1, Wr1, Wl2, Wr2);
    tohalf_kernel<<<convBlocks, 256>>>((const float4*)x, (uint2*)x16p, n4);
    deg_kernel<<<edgeGrpBlocks, 256>>>(eix, nE);
    blocksum_kernel<<<scanBlocks, 256>>>(nN);
    scanpart_kernel<<<1, 128>>>(scanBlocks);
    offsets_kernel<<<scanBlocks, 256>>>(nN, nE);
    fill_kernel<<<edgeGrpBlocks, 256>>>(eix, nE);

    // ---- layer 1: emits only the fp16 plane h16 ----
    agg16_kernel<<<aggBlocks, 256>>>((const uint2*)x16p, nN);
    gemm_f16_kernel<true, true><<<gemmBlocks, 256, SM_TOTAL>>>(
        (const uint2*)x16p, 0, b1, nullptr, (uint32_t*)h16p, nN);

    // ---- layer 2: fp32 output ----
    agg16_kernel<<<aggBlocks, 256>>>((const uint2*)h16p, nN);
    gemm_f16_kernel<false, false><<<gemmBlocks, 256, SM_TOTAL>>>(
        (const uint2*)h16p, 1, b2, out, nullptr, nN);
}